// round 13
// baseline (speedup 1.0000x reference)
#include <cuda_runtime.h>
#include <cstdint>

// ---------------- problem constants ----------------
#define BB   16
#define CC   256
#define HH   64
#define WW   64
#define NHH  8
#define DHH  64
#define CIN  260
#define KPAD 264
#define DQKV 512
#define HWN  4096
#define PLEN 128
#define SCALE 0.08838834764831843f  // 1/sqrt(128)

typedef unsigned long long u64;

// ---------------- f32x2 packed-FMA helpers ----------------
__device__ __forceinline__ u64 pk2(float x) {
    u64 r; asm("mov.b64 %0, {%1, %1};" : "=l"(r) : "f"(x)); return r;
}
__device__ __forceinline__ void fma2(u64 &d, u64 a, u64 b) {
    asm("fma.rn.f32x2 %0, %1, %2, %3;" : "=l"(d) : "l"(a), "l"(b), "l"(d));
}
__device__ __forceinline__ float2 up2(u64 v) {
    float lo, hi; asm("mov.b64 {%0, %1}, %2;" : "=f"(lo), "=f"(hi) : "l"(v));
    return make_float2(lo, hi);
}

// ---------------- tf32 helpers ----------------
__device__ __forceinline__ uint32_t f2tf32(float f) {
    uint32_t u;
    asm("cvt.rna.tf32.f32 %0, %1;" : "=r"(u) : "f"(f));
    return u;
}
__device__ __forceinline__ void mma_tf32(float c[4], const uint32_t a[4],
                                         const uint32_t bfr[2]) {
    asm volatile(
        "mma.sync.aligned.m16n8k8.row.col.f32.tf32.tf32.f32 "
        "{%0,%1,%2,%3}, {%4,%5,%6,%7}, {%8,%9}, {%0,%1,%2,%3};"
        : "+f"(c[0]), "+f"(c[1]), "+f"(c[2]), "+f"(c[3])
        : "r"(a[0]), "r"(a[1]), "r"(a[2]), "r"(a[3]),
          "r"(bfr[0]), "r"(bfr[1]));
}

// ---------------- device scratch ----------------
#define TSZ ((size_t)BB * DQKV * HWN)
__device__ float g_Q [TSZ];
__device__ float g_K [TSZ];
__device__ float g_V [TSZ];
__device__ float g_QT[TSZ];
__device__ float g_KT[TSZ];
__device__ float g_VT[TSZ];
__device__ float g_A [TSZ];    // a_w in [b][p][ch]
__device__ float g_AT[TSZ];    // a_h in [b][p][ch]
__device__ float g_P [(size_t)BB * NHH * HH * WW * PLEN];
__device__ float g_XT[(size_t)BB * HWN * KPAD];

// =====================================================================
// Kernel 0: transpose xp = concat(x,pos) -> g_XT [b][p][264]
// =====================================================================
__global__ __launch_bounds__(256) void xpose_x(
    const float* __restrict__ x, const float* __restrict__ pos)
{
    __shared__ float tile[64][65];
    int t = threadIdx.x;
    int p0 = blockIdx.x * 64, c0 = blockIdx.y * 64, b = blockIdx.z;
    #pragma unroll
    for (int r = 0; r < 16; r++) {
        int idx = r * 256 + t;
        int cc = idx >> 6, pp = idx & 63;
        int c = c0 + cc;
        float v = 0.0f;
        if (c < CC)       v = x[((size_t)b * CC + c) * HWN + p0 + pp];
        else if (c < CIN) v = pos[(size_t)(c - CC) * HWN + p0 + pp];
        tile[cc][pp] = v;
    }
    __syncthreads();
    #pragma unroll
    for (int r = 0; r < 16; r++) {
        int idx = r * 256 + t;
        int pp = idx >> 6, cc = idx & 63;
        int c = c0 + cc;
        if (c < KPAD)
            g_XT[((size_t)b * HWN + p0 + pp) * KPAD + c] = tile[cc][pp];
    }
}

// =====================================================================
// Kernel 1: QKV projection via mma.sync tf32 (m16n8k8).
// =====================================================================
__global__ __launch_bounds__(256, 2) void qkv_mma(
    const float* __restrict__ Wq, const float* __restrict__ bq,
    const float* __restrict__ Wk, const float* __restrict__ bk,
    const float* __restrict__ Wv, const float* __restrict__ bv)
{
    int pT = blockIdx.x, nT = blockIdx.y, b = blockIdx.z;
    int which = nT >> 2;
    int mOff  = (nT & 3) * 128;
    const float* Wt   = (which == 0) ? Wq : (which == 1) ? Wk : Wv;
    const float* bias = (which == 0) ? bq : (which == 1) ? bk : bv;
    float*       outp = (which == 0) ? g_Q : (which == 1) ? g_K : g_V;

    __shared__ uint32_t As[128][36];
    __shared__ uint32_t Bs[128][36];

    int t = threadIdx.x, lane = t & 31, wid = t >> 5;
    int g = lane >> 2, tig = lane & 3;
    int wm = (wid >> 2) * 64, wn = (wid & 3) * 32;

    const float* xt = g_XT + ((size_t)b * HWN + (size_t)pT * 128) * KPAD;

    float c[4][4][4];
    #pragma unroll
    for (int mi = 0; mi < 4; mi++)
        #pragma unroll
        for (int ni = 0; ni < 4; ni++)
            #pragma unroll
            for (int e = 0; e < 4; e++) c[mi][ni][e] = 0.0f;

    for (int c0 = 0; c0 < 9; c0++) {
        int kBase = c0 * 32;
        #pragma unroll
        for (int r = 0; r < 4; r++) {
            int idx = r * 256 + t;
            int row = idx >> 3, q = idx & 7;
            int k4 = kBase + q * 4;
            float4 va = make_float4(0.f, 0.f, 0.f, 0.f);
            if (k4 <= CIN - 4)
                va = *(const float4*)(Wt + (size_t)(mOff + row) * CIN + k4);
            As[row][q * 4 + 0] = f2tf32(va.x);
            As[row][q * 4 + 1] = f2tf32(va.y);
            As[row][q * 4 + 2] = f2tf32(va.z);
            As[row][q * 4 + 3] = f2tf32(va.w);
            float4 vb = make_float4(0.f, 0.f, 0.f, 0.f);
            if (k4 <= KPAD - 4)
                vb = *(const float4*)(xt + (size_t)row * KPAD + k4);
            Bs[row][q * 4 + 0] = f2tf32(vb.x);
            Bs[row][q * 4 + 1] = f2tf32(vb.y);
            Bs[row][q * 4 + 2] = f2tf32(vb.z);
            Bs[row][q * 4 + 3] = f2tf32(vb.w);
        }
        __syncthreads();
        #pragma unroll
        for (int ks = 0; ks < 4; ks++) {
            int kk = ks * 8;
            uint32_t a[4][4], bfr[4][2];
            #pragma unroll
            for (int mi = 0; mi < 4; mi++) {
                int row = wm + mi * 16 + g;
                a[mi][0] = As[row][kk + tig];
                a[mi][1] = As[row + 8][kk + tig];
                a[mi][2] = As[row][kk + tig + 4];
                a[mi][3] = As[row + 8][kk + tig + 4];
            }
            #pragma unroll
            for (int ni = 0; ni < 4; ni++) {
                int col = wn + ni * 8 + g;
                bfr[ni][0] = Bs[col][kk + tig];
                bfr[ni][1] = Bs[col][kk + tig + 4];
            }
            #pragma unroll
            for (int mi = 0; mi < 4; mi++)
                #pragma unroll
                for (int ni = 0; ni < 4; ni++)
                    mma_tf32(c[mi][ni], a[mi], bfr[ni]);
        }
        __syncthreads();
    }

    #pragma unroll
    for (int mi = 0; mi < 4; mi++) {
        int row0 = wm + mi * 16 + g;
        float bi0 = bias[mOff + row0];
        float bi1 = bias[mOff + row0 + 8];
        float* o0 = outp + ((size_t)b * DQKV + mOff + row0) * HWN + (size_t)pT * 128;
        float* o1 = o0 + (size_t)8 * HWN;
        #pragma unroll
        for (int ni = 0; ni < 4; ni++) {
            int col = wn + ni * 8 + tig * 2;
            float2 v0 = make_float2(c[mi][ni][0] + bi0, c[mi][ni][1] + bi0);
            float2 v1 = make_float2(c[mi][ni][2] + bi1, c[mi][ni][3] + bi1);
            *(float2*)(o0 + col) = v0;
            *(float2*)(o1 + col) = v1;
        }
    }
}

// =====================================================================
// Kernel 2: transpose each 64x64 image of Q,K,V -> QT,KT,VT
// =====================================================================
__global__ __launch_bounds__(256) void transpose3_kernel()
{
    const float* src = (blockIdx.y == 0) ? g_Q : (blockIdx.y == 1) ? g_K : g_V;
    float*       dst = (blockIdx.y == 0) ? g_QT : (blockIdx.y == 1) ? g_KT : g_VT;
    size_t base = (size_t)blockIdx.x * HWN;
    __shared__ float sm[64][65];
    int t = threadIdx.x;
    #pragma unroll
    for (int r = 0; r < 16; r++) {
        int idx = r * 256 + t;
        sm[idx >> 6][idx & 63] = src[base + idx];
    }
    __syncthreads();
    #pragma unroll
    for (int r = 0; r < 16; r++) {
        int idx = r * 256 + t;
        dst[base + idx] = sm[idx & 63][idx >> 6];
    }
}

// =====================================================================
// Kernel 3: row logits (f32x2). writes RAW scaled logits (low half).
// =====================================================================
__global__ __launch_bounds__(256) void logits_row_kernel()
{
    int i = blockIdx.x, h = blockIdx.y, b = blockIdx.z;
    __shared__ float qs[64][64];
    __shared__ float ks[64][64];
    size_t base = ((size_t)(b * DQKV + h * DHH)) * HWN + i * WW;
    int t = threadIdx.x;
    #pragma unroll
    for (int r = 0; r < 16; r++) {
        int idx = r * 256 + t;
        int d = idx >> 6, j = idx & 63;
        qs[d][j] = g_Q[base + (size_t)d * HWN + j];
        ks[d][j] = g_K[base + (size_t)d * HWN + j];
    }
    __syncthreads();
    int tx = t & 15, ty = t >> 4;
    u64 acc[4][2];
    #pragma unroll
    for (int u = 0; u < 4; u++) { acc[u][0] = 0ull; acc[u][1] = 0ull; }
    #pragma unroll
    for (int d = 0; d < 64; d++) {
        float4 q4 = *(float4*)&qs[d][ty * 4];
        const u64* kp = (const u64*)&ks[d][tx * 4];
        u64 k0 = kp[0], k1 = kp[1];
        u64 qa[4] = {pk2(q4.x), pk2(q4.y), pk2(q4.z), pk2(q4.w)};
        #pragma unroll
        for (int u = 0; u < 4; u++) {
            fma2(acc[u][0], qa[u], k0);
            fma2(acc[u][1], qa[u], k1);
        }
    }
    size_t pbase = (((size_t)((b * NHH + h) * HH + i)) * WW) * PLEN;
    #pragma unroll
    for (int u = 0; u < 4; u++) {
        int j = ty * 4 + u;
        float2 p0 = up2(acc[u][0]), p1 = up2(acc[u][1]);
        float4 o = make_float4(p0.x * SCALE, p0.y * SCALE, p1.x * SCALE, p1.y * SCALE);
        *(float4*)&g_P[pbase + (size_t)j * PLEN + tx * 4] = o;
    }
}

// =====================================================================
// Kernel 4: column logits + JOINT SOFTMAX. block (j, h, b).
// Computes col half in smem, reads raw row half from g_P, normalizes
// jointly over 128, writes BOTH halves normalized.
// =====================================================================
__global__ __launch_bounds__(256) void logits_col_kernel()
{
    int j = blockIdx.x, h = blockIdx.y, b = blockIdx.z;
    __shared__ float qs[64][64];
    __shared__ float ks[64][64];
    __shared__ float ls[64][68];   // col logits [i][k], padded
    size_t base = ((size_t)(b * DQKV + h * DHH)) * HWN + j * HH;
    int t = threadIdx.x;
    #pragma unroll
    for (int r = 0; r < 16; r++) {
        int idx = r * 256 + t;
        int d = idx >> 6, ii = idx & 63;
        qs[d][ii] = g_QT[base + (size_t)d * HWN + ii];
        ks[d][ii] = g_KT[base + (size_t)d * HWN + ii];
    }
    __syncthreads();
    int tx = t & 15, ty = t >> 4;
    u64 acc[4][2];
    #pragma unroll
    for (int u = 0; u < 4; u++) { acc[u][0] = 0ull; acc[u][1] = 0ull; }
    #pragma unroll
    for (int d = 0; d < 64; d++) {
        float4 q4 = *(float4*)&qs[d][ty * 4];
        const u64* kp = (const u64*)&ks[d][tx * 4];
        u64 k0 = kp[0], k1 = kp[1];
        u64 qa[4] = {pk2(q4.x), pk2(q4.y), pk2(q4.z), pk2(q4.w)};
        #pragma unroll
        for (int u = 0; u < 4; u++) {
            fma2(acc[u][0], qa[u], k0);
            fma2(acc[u][1], qa[u], k1);
        }
    }
    // stage scaled col logits into smem: ls[i][k]
    #pragma unroll
    for (int u = 0; u < 4; u++) {
        int i = ty * 4 + u;
        float2 p0 = up2(acc[u][0]), p1 = up2(acc[u][1]);
        float4 o = make_float4(p0.x * SCALE, p0.y * SCALE, p1.x * SCALE, p1.y * SCALE);
        *(float4*)&ls[i][tx * 4] = o;
    }
    __syncthreads();

    // joint softmax: query i = t>>2, lane group g2 = t&3 handles 32 of 128.
    size_t pbh = ((size_t)((b * NHH + h) * HH)) * WW * PLEN;
    {
        int i = t >> 2, g2 = t & 3;
        size_t pq = pbh + ((size_t)i * WW + j) * PLEN;
        float v[32];
        if (g2 < 2) {
            const float4* src = (const float4*)(g_P + pq + g2 * 32);
            #pragma unroll
            for (int r = 0; r < 8; r++) {
                float4 f = src[r];
                v[r * 4] = f.x; v[r * 4 + 1] = f.y;
                v[r * 4 + 2] = f.z; v[r * 4 + 3] = f.w;
            }
        } else {
            const float4* src = (const float4*)&ls[i][(g2 - 2) * 32];
            #pragma unroll
            for (int r = 0; r < 8; r++) {
                float4 f = src[r];
                v[r * 4] = f.x; v[r * 4 + 1] = f.y;
                v[r * 4 + 2] = f.z; v[r * 4 + 3] = f.w;
            }
        }
        float m = v[0];
        #pragma unroll
        for (int e = 1; e < 32; e++) m = fmaxf(m, v[e]);
        m = fmaxf(m, __shfl_xor_sync(0xffffffffu, m, 1));
        m = fmaxf(m, __shfl_xor_sync(0xffffffffu, m, 2));
        float s = 0.0f;
        #pragma unroll
        for (int e = 0; e < 32; e++) { v[e] = __expf(v[e] - m); s += v[e]; }
        s += __shfl_xor_sync(0xffffffffu, s, 1);
        s += __shfl_xor_sync(0xffffffffu, s, 2);
        float inv = 1.0f / s;
        float4* dst = (float4*)(g_P + pq + g2 * 32);   // g2:0,1->row half; 2,3->col half
        #pragma unroll
        for (int r = 0; r < 8; r++) {
            float4 o = make_float4(v[r * 4] * inv, v[r * 4 + 1] * inv,
                                   v[r * 4 + 2] * inv, v[r * 4 + 3] * inv);
            dst[r] = o;
        }
    }
}

// =====================================================================
// Kernel 6: row attention (f32x2, R11 form). block (i,h,b).
// =====================================================================
__global__ __launch_bounds__(256) void attn_row_kernel()
{
    int i = blockIdx.x, h = blockIdx.y, b = blockIdx.z;
    __shared__ float vsT[64][68];
    __shared__ float psT[64][68];
    size_t vbase = ((size_t)(b * DQKV + h * DHH)) * HWN + i * WW;
    size_t pbase = (((size_t)((b * NHH + h) * HH + i)) * WW) * PLEN;
    int t = threadIdx.x;
    #pragma unroll
    for (int r = 0; r < 16; r++) {
        int idx = r * 256 + t;
        int a = idx >> 6, k = idx & 63;
        vsT[k][a] = g_V[vbase + (size_t)a * HWN + k];
        psT[k][a] = g_P[pbase + (size_t)a * PLEN + k];
    }
    __syncthreads();
    int tx = t & 15, ty = t >> 4;
    u64 acc[4][2];
    #pragma unroll
    for (int u = 0; u < 4; u++) { acc[u][0] = 0ull; acc[u][1] = 0ull; }
    #pragma unroll
    for (int k = 0; k < 64; k++) {
        float4 v4 = *(float4*)&vsT[k][ty * 4];
        const u64* pp = (const u64*)&psT[k][tx * 4];
        u64 p0 = pp[0], p1 = pp[1];
        u64 va[4] = {pk2(v4.x), pk2(v4.y), pk2(v4.z), pk2(v4.w)};
        #pragma unroll
        for (int u = 0; u < 4; u++) {
            fma2(acc[u][0], va[u], p0);
            fma2(acc[u][1], va[u], p1);
        }
    }
    float av[4][4];
    #pragma unroll
    for (int u = 0; u < 4; u++) {
        float2 a0 = up2(acc[u][0]), a1 = up2(acc[u][1]);
        av[u][0] = a0.x; av[u][1] = a0.y; av[u][2] = a1.x; av[u][3] = a1.y;
    }
    int chb = h * DHH + ty * 4;
    #pragma unroll
    for (int cc = 0; cc < 4; cc++) {
        int p = i * WW + tx * 4 + cc;
        *(float4*)(g_A + ((size_t)b * HWN + p) * DQKV + chb) =
            make_float4(av[0][cc], av[1][cc], av[2][cc], av[3][cc]);
    }
}

// =====================================================================
// Kernel 7: column attention (f32x2, R11 form). block (j,h,b).
// =====================================================================
__global__ __launch_bounds__(256) void attn_col_kernel()
{
    int j = blockIdx.x, h = blockIdx.y, b = blockIdx.z;
    __shared__ float vsT[64][68];
    __shared__ float psT[64][68];
    size_t vbase = ((size_t)(b * DQKV + h * DHH)) * HWN + j * HH;
    size_t pcol  = ((size_t)((b * NHH + h) * HH) * WW + j) * PLEN + 64;
    int t = threadIdx.x;
    #pragma unroll
    for (int r = 0; r < 16; r++) {
        int idx = r * 256 + t;
        int a = idx >> 6, k = idx & 63;
        vsT[k][a] = g_VT[vbase + (size_t)a * HWN + k];
        psT[k][a] = g_P[pcol + (size_t)a * (WW * PLEN) + k];
    }
    __syncthreads();
    int tx = t & 15, ty = t >> 4;
    u64 acc[4][2];
    #pragma unroll
    for (int u = 0; u < 4; u++) { acc[u][0] = 0ull; acc[u][1] = 0ull; }
    #pragma unroll
    for (int k = 0; k < 64; k++) {
        float4 v4 = *(float4*)&vsT[k][ty * 4];
        const u64* pp = (const u64*)&psT[k][tx * 4];
        u64 p0 = pp[0], p1 = pp[1];
        u64 va[4] = {pk2(v4.x), pk2(v4.y), pk2(v4.z), pk2(v4.w)};
        #pragma unroll
        for (int u = 0; u < 4; u++) {
            fma2(acc[u][0], va[u], p0);
            fma2(acc[u][1], va[u], p1);
        }
    }
    float av[4][4];
    #pragma unroll
    for (int u = 0; u < 4; u++) {
        float2 a0 = up2(acc[u][0]), a1 = up2(acc[u][1]);
        av[u][0] = a0.x; av[u][1] = a0.y; av[u][2] = a1.x; av[u][3] = a1.y;
    }
    int chb = h * DHH + ty * 4;
    #pragma unroll
    for (int cc = 0; cc < 4; cc++) {
        int p = (tx * 4 + cc) * WW + j;
        *(float4*)(g_AT + ((size_t)b * HWN + p) * DQKV + chb) =
            make_float4(av[0][cc], av[1][cc], av[2][cc], av[3][cc]);
    }
}

// =====================================================================
// Kernel 9: output projection + residual via mma.sync tf32.
// =====================================================================
__global__ __launch_bounds__(256, 2) void proj_mma(
    const float* __restrict__ x, const float* __restrict__ Wo,
    const float* __restrict__ bo, float* __restrict__ out)
{
    int pT = blockIdx.x, mT = blockIdx.y, b = blockIdx.z;
    int mOff = mT * 128;

    __shared__ uint32_t As[128][36];
    __shared__ uint32_t Bs[128][36];

    int t = threadIdx.x, lane = t & 31, wid = t >> 5;
    int g = lane >> 2, tig = lane & 3;
    int wm = (wid >> 2) * 64, wn = (wid & 3) * 32;

    const float* a2w = g_A  + ((size_t)b * HWN + (size_t)pT * 128) * DQKV;
    const float* a2h = g_AT + ((size_t)b * HWN + (size_t)pT * 128) * DQKV;

    float c[4][4][4];
    #pragma unroll
    for (int mi = 0; mi < 4; mi++)
        #pragma unroll
        for (int ni = 0; ni < 4; ni++)
            #pragma unroll
            for (int e = 0; e < 4; e++) c[mi][ni][e] = 0.0f;

    for (int c0 = 0; c0 < 16; c0++) {
        int kBase = c0 * 32;
        #pragma unroll
        for (int r = 0; r < 4; r++) {
            int idx = r * 256 + t;
            int row = idx >> 3, q = idx & 7;
            int k4 = kBase + q * 4;
            float4 va = *(const float4*)(Wo + (size_t)(mOff + row) * DQKV + k4);
            As[row][q * 4 + 0] = f2tf32(va.x);
            As[row][q * 4 + 1] = f2tf32(va.y);
            As[row][q * 4 + 2] = f2tf32(va.z);
            As[row][q * 4 + 3] = f2tf32(va.w);
            float4 vb = *(const float4*)(a2w + (size_t)row * DQKV + k4);
            float4 vh = *(const float4*)(a2h + (size_t)row * DQKV + k4);
            Bs[row][q * 4 + 0] = f2tf32(vb.x + vh.x);
            Bs[row][q * 4 + 1] = f2tf32(vb.y + vh.y);
            Bs[row][q * 4 + 2] = f2tf32(vb.z + vh.z);
            Bs[row][q * 4 + 3] = f2tf32(vb.w + vh.w);
        }
        __syncthreads();
        #pragma unroll
        for (int ks = 0; ks < 4; ks++) {
            int kk = ks * 8;
            uint32_t a[4][4], bfr[4][2];
            #pragma unroll
            for (int mi = 0; mi < 4; mi++) {
                int row = wm + mi * 16 + g;
                a[mi][0] = As[row][kk + tig];
                a[mi][1] = As[row + 8][kk + tig];
                a[mi][2] = As[row][kk + tig + 4];
                a[mi][3] = As[row + 8][kk + tig + 4];
            }
            #pragma unroll
            for (int ni = 0; ni < 4; ni++) {
                int col = wn + ni * 8 + g;
                bfr[ni][0] = Bs[col][kk + tig];
                bfr[ni][1] = Bs[col][kk + tig + 4];
            }
            #pragma unroll
            for (int mi = 0; mi < 4; mi++)
                #pragma unroll
                for (int ni = 0; ni < 4; ni++)
                    mma_tf32(c[mi][ni], a[mi], bfr[ni]);
        }
        __syncthreads();
    }

    #pragma unroll
    for (int mi = 0; mi < 4; mi++) {
        int row0 = wm + mi * 16 + g;
        int ch0 = mOff + row0;
        float bi0 = bo[ch0];
        float bi1 = bo[ch0 + 8];
        size_t base0 = ((size_t)b * CC + ch0) * HWN + (size_t)pT * 128;
        size_t base1 = base0 + (size_t)8 * HWN;
        #pragma unroll
        for (int ni = 0; ni < 4; ni++) {
            int col = wn + ni * 8 + tig * 2;
            float2 x0 = *(const float2*)(x + base0 + col);
            float2 x1 = *(const float2*)(x + base1 + col);
            float2 v0 = make_float2(c[mi][ni][0] + bi0 + x0.x,
                                    c[mi][ni][1] + bi0 + x0.y);
            float2 v1 = make_float2(c[mi][ni][2] + bi1 + x1.x,
                                    c[mi][ni][3] + bi1 + x1.y);
            *(float2*)(out + base0 + col) = v0;
            *(float2*)(out + base1 + col) = v1;
        }
    }
}

// =====================================================================
extern "C" void kernel_launch(void* const* d_in, const int* in_sizes, int n_in,
                              void* d_out, int out_size)
{
    const float* x   = (const float*)d_in[0];
    const float* pos = (const float*)d_in[1];
    const float* Wk  = (const float*)d_in[2];
    const float* bk  = (const float*)d_in[3];
    const float* Wq  = (const float*)d_in[4];
    const float* bq  = (const float*)d_in[5];
    const float* Wv  = (const float*)d_in[6];
    const float* bv  = (const float*)d_in[7];
    const float* Wo  = (const float*)d_in[8];
    const float* bo  = (const float*)d_in[9];
    float* out = (float*)d_out;

    xpose_x<<<dim3(64, 5, BB), 256>>>(x, pos);
    qkv_mma<<<dim3(32, 12, BB), 256>>>(Wq, bq, Wk, bk, Wv, bv);
    transpose3_kernel<<<dim3(BB * DQKV, 3), 256>>>();
    logits_row_kernel<<<dim3(HH, NHH, BB), 256>>>();
    logits_col_kernel<<<dim3(WW, NHH, BB), 256>>>();
    attn_row_kernel<<<dim3(HH, NHH, BB), 256>>>();
    attn_col_kernel<<<dim3(WW, NHH, BB), 256>>>();
    proj_mma<<<dim3(32, 2, BB), 256>>>(x, Wo, bo, out);
}

// round 14
// speedup vs baseline: 1.1263x; 1.1263x over previous
#include <cuda_runtime.h>
#include <cuda_fp16.h>
#include <cstdint>

// ---------------- problem constants ----------------
#define BB   16
#define CC   256
#define HH   64
#define WW   64
#define NHH  8
#define DHH  64
#define CIN  260
#define KPAD 264
#define DQKV 512
#define HWN  4096
#define PLEN 128
#define SCALE 0.08838834764831843f  // 1/sqrt(128)

typedef unsigned long long u64;

// ---------------- f32x2 packed-FMA helpers ----------------
__device__ __forceinline__ u64 pk2(float x) {
    u64 r; asm("mov.b64 %0, {%1, %1};" : "=l"(r) : "f"(x)); return r;
}
__device__ __forceinline__ void fma2(u64 &d, u64 a, u64 b) {
    asm("fma.rn.f32x2 %0, %1, %2, %3;" : "=l"(d) : "l"(a), "l"(b), "l"(d));
}
__device__ __forceinline__ float2 up2(u64 v) {
    float lo, hi; asm("mov.b64 {%0, %1}, %2;" : "=f"(lo), "=f"(hi) : "l"(v));
    return make_float2(lo, hi);
}

// ---------------- tf32 helpers ----------------
__device__ __forceinline__ uint32_t f2tf32(float f) {
    uint32_t u;
    asm("cvt.rna.tf32.f32 %0, %1;" : "=r"(u) : "f"(f));
    return u;
}
__device__ __forceinline__ void mma_tf32(float c[4], const uint32_t a[4],
                                         const uint32_t bfr[2]) {
    asm volatile(
        "mma.sync.aligned.m16n8k8.row.col.f32.tf32.tf32.f32 "
        "{%0,%1,%2,%3}, {%4,%5,%6,%7}, {%8,%9}, {%0,%1,%2,%3};"
        : "+f"(c[0]), "+f"(c[1]), "+f"(c[2]), "+f"(c[3])
        : "r"(a[0]), "r"(a[1]), "r"(a[2]), "r"(a[3]),
          "r"(bfr[0]), "r"(bfr[1]));
}

// ---------------- fp16 pack/unpack helpers ----------------
__device__ __forceinline__ float4 ldh4(const __half* p) {
    uint2 u = *(const uint2*)p;
    __half2 h0 = *(__half2*)&u.x, h1 = *(__half2*)&u.y;
    float2 f0 = __half22float2(h0), f1 = __half22float2(h1);
    return make_float4(f0.x, f0.y, f1.x, f1.y);
}
__device__ __forceinline__ void sth4(__half* p, float4 v) {
    uint2 u;
    *(__half2*)&u.x = __floats2half2_rn(v.x, v.y);
    *(__half2*)&u.y = __floats2half2_rn(v.z, v.w);
    *(uint2*)p = u;
}

// ---------------- device scratch (all fp16) ----------------
#define TSZ ((size_t)BB * DQKV * HWN)
__device__ __half g_Q [TSZ];
__device__ __half g_K [TSZ];
__device__ __half g_V [TSZ];
__device__ __half g_QT[TSZ];
__device__ __half g_KT[TSZ];
__device__ __half g_VT[TSZ];
__device__ __half g_A [TSZ];    // a_w in [b][p][ch]
__device__ __half g_AT[TSZ];    // a_h in [b][p][ch]
__device__ __half g_P [(size_t)BB * NHH * HH * WW * PLEN];
__device__ __half g_XT[(size_t)BB * HWN * KPAD];

// =====================================================================
// Kernel 0: transpose xp = concat(x,pos) -> g_XT [b][p][264] (fp16)
// =====================================================================
__global__ __launch_bounds__(256) void xpose_x(
    const float* __restrict__ x, const float* __restrict__ pos)
{
    __shared__ float tile[64][65];
    int t = threadIdx.x;
    int p0 = blockIdx.x * 64, c0 = blockIdx.y * 64, b = blockIdx.z;
    #pragma unroll
    for (int r = 0; r < 16; r++) {
        int idx = r * 256 + t;
        int cc = idx >> 6, pp = idx & 63;
        int c = c0 + cc;
        float v = 0.0f;
        if (c < CC)       v = x[((size_t)b * CC + c) * HWN + p0 + pp];
        else if (c < CIN) v = pos[(size_t)(c - CC) * HWN + p0 + pp];
        tile[cc][pp] = v;
    }
    __syncthreads();
    #pragma unroll
    for (int r = 0; r < 16; r++) {
        int idx = r * 256 + t;
        int pp = idx >> 6, cc = idx & 63;
        int c = c0 + cc;
        if (c < KPAD)
            g_XT[((size_t)b * HWN + p0 + pp) * KPAD + c] = __float2half(tile[cc][pp]);
    }
}

// =====================================================================
// Kernel 1: QKV projection via mma.sync tf32; fp16 in (XT) / fp16 out.
// =====================================================================
__global__ __launch_bounds__(256, 2) void qkv_mma(
    const float* __restrict__ Wq, const float* __restrict__ bq,
    const float* __restrict__ Wk, const float* __restrict__ bk,
    const float* __restrict__ Wv, const float* __restrict__ bv)
{
    int pT = blockIdx.x, nT = blockIdx.y, b = blockIdx.z;
    int which = nT >> 2;
    int mOff  = (nT & 3) * 128;
    const float* Wt   = (which == 0) ? Wq : (which == 1) ? Wk : Wv;
    const float* bias = (which == 0) ? bq : (which == 1) ? bk : bv;
    __half*      outp = (which == 0) ? g_Q : (which == 1) ? g_K : g_V;

    __shared__ uint32_t As[128][36];
    __shared__ uint32_t Bs[128][36];

    int t = threadIdx.x, lane = t & 31, wid = t >> 5;
    int g = lane >> 2, tig = lane & 3;
    int wm = (wid >> 2) * 64, wn = (wid & 3) * 32;

    const __half* xt = g_XT + ((size_t)b * HWN + (size_t)pT * 128) * KPAD;

    float c[4][4][4];
    #pragma unroll
    for (int mi = 0; mi < 4; mi++)
        #pragma unroll
        for (int ni = 0; ni < 4; ni++)
            #pragma unroll
            for (int e = 0; e < 4; e++) c[mi][ni][e] = 0.0f;

    for (int c0 = 0; c0 < 9; c0++) {
        int kBase = c0 * 32;
        #pragma unroll
        for (int r = 0; r < 4; r++) {
            int idx = r * 256 + t;
            int row = idx >> 3, q = idx & 7;
            int k4 = kBase + q * 4;
            float4 va = make_float4(0.f, 0.f, 0.f, 0.f);
            if (k4 <= CIN - 4)
                va = *(const float4*)(Wt + (size_t)(mOff + row) * CIN + k4);
            As[row][q * 4 + 0] = f2tf32(va.x);
            As[row][q * 4 + 1] = f2tf32(va.y);
            As[row][q * 4 + 2] = f2tf32(va.z);
            As[row][q * 4 + 3] = f2tf32(va.w);
            float4 vb = make_float4(0.f, 0.f, 0.f, 0.f);
            if (k4 <= KPAD - 4)
                vb = ldh4(xt + (size_t)row * KPAD + k4);
            Bs[row][q * 4 + 0] = f2tf32(vb.x);
            Bs[row][q * 4 + 1] = f2tf32(vb.y);
            Bs[row][q * 4 + 2] = f2tf32(vb.z);
            Bs[row][q * 4 + 3] = f2tf32(vb.w);
        }
        __syncthreads();
        #pragma unroll
        for (int ks = 0; ks < 4; ks++) {
            int kk = ks * 8;
            uint32_t a[4][4], bfr[4][2];
            #pragma unroll
            for (int mi = 0; mi < 4; mi++) {
                int row = wm + mi * 16 + g;
                a[mi][0] = As[row][kk + tig];
                a[mi][1] = As[row + 8][kk + tig];
                a[mi][2] = As[row][kk + tig + 4];
                a[mi][3] = As[row + 8][kk + tig + 4];
            }
            #pragma unroll
            for (int ni = 0; ni < 4; ni++) {
                int col = wn + ni * 8 + g;
                bfr[ni][0] = Bs[col][kk + tig];
                bfr[ni][1] = Bs[col][kk + tig + 4];
            }
            #pragma unroll
            for (int mi = 0; mi < 4; mi++)
                #pragma unroll
                for (int ni = 0; ni < 4; ni++)
                    mma_tf32(c[mi][ni], a[mi], bfr[ni]);
        }
        __syncthreads();
    }

    #pragma unroll
    for (int mi = 0; mi < 4; mi++) {
        int row0 = wm + mi * 16 + g;
        float bi0 = bias[mOff + row0];
        float bi1 = bias[mOff + row0 + 8];
        __half* o0 = outp + ((size_t)b * DQKV + mOff + row0) * HWN + (size_t)pT * 128;
        __half* o1 = o0 + (size_t)8 * HWN;
        #pragma unroll
        for (int ni = 0; ni < 4; ni++) {
            int col = wn + ni * 8 + tig * 2;
            *(__half2*)(o0 + col) = __floats2half2_rn(c[mi][ni][0] + bi0,
                                                      c[mi][ni][1] + bi0);
            *(__half2*)(o1 + col) = __floats2half2_rn(c[mi][ni][2] + bi1,
                                                      c[mi][ni][3] + bi1);
        }
    }
}

// =====================================================================
// Kernel 2: transpose each 64x64 image of Q,K,V -> QT,KT,VT (fp16)
// =====================================================================
__global__ __launch_bounds__(256) void transpose3_kernel()
{
    const __half* src = (blockIdx.y == 0) ? g_Q : (blockIdx.y == 1) ? g_K : g_V;
    __half*       dst = (blockIdx.y == 0) ? g_QT : (blockIdx.y == 1) ? g_KT : g_VT;
    size_t base = (size_t)blockIdx.x * HWN;
    __shared__ __half sm[64][65];
    int t = threadIdx.x;
    #pragma unroll
    for (int r = 0; r < 16; r++) {
        int idx = r * 256 + t;
        sm[idx >> 6][idx & 63] = src[base + idx];
    }
    __syncthreads();
    #pragma unroll
    for (int r = 0; r < 16; r++) {
        int idx = r * 256 + t;
        dst[base + idx] = sm[idx & 63][idx >> 6];
    }
}

// =====================================================================
// Kernel 3: row logits (f32x2). fp16 in, fp16 raw logits out.
// =====================================================================
__global__ __launch_bounds__(256) void logits_row_kernel()
{
    int i = blockIdx.x, h = blockIdx.y, b = blockIdx.z;
    __shared__ float qs[64][64];
    __shared__ float ks[64][64];
    size_t base = ((size_t)(b * DQKV + h * DHH)) * HWN + i * WW;
    int t = threadIdx.x;
    #pragma unroll
    for (int r = 0; r < 16; r++) {
        int idx = r * 256 + t;
        int d = idx >> 6, j = idx & 63;
        qs[d][j] = __half2float(g_Q[base + (size_t)d * HWN + j]);
        ks[d][j] = __half2float(g_K[base + (size_t)d * HWN + j]);
    }
    __syncthreads();
    int tx = t & 15, ty = t >> 4;
    u64 acc[4][2];
    #pragma unroll
    for (int u = 0; u < 4; u++) { acc[u][0] = 0ull; acc[u][1] = 0ull; }
    #pragma unroll
    for (int d = 0; d < 64; d++) {
        float4 q4 = *(float4*)&qs[d][ty * 4];
        const u64* kp = (const u64*)&ks[d][tx * 4];
        u64 k0 = kp[0], k1 = kp[1];
        u64 qa[4] = {pk2(q4.x), pk2(q4.y), pk2(q4.z), pk2(q4.w)};
        #pragma unroll
        for (int u = 0; u < 4; u++) {
            fma2(acc[u][0], qa[u], k0);
            fma2(acc[u][1], qa[u], k1);
        }
    }
    size_t pbase = (((size_t)((b * NHH + h) * HH + i)) * WW) * PLEN;
    #pragma unroll
    for (int u = 0; u < 4; u++) {
        int j = ty * 4 + u;
        float2 p0 = up2(acc[u][0]), p1 = up2(acc[u][1]);
        sth4(&g_P[pbase + (size_t)j * PLEN + tx * 4],
             make_float4(p0.x * SCALE, p0.y * SCALE, p1.x * SCALE, p1.y * SCALE));
    }
}

// =====================================================================
// Kernel 4: column logits (f32x2). fp16 in, fp16 raw logits out.
// =====================================================================
__global__ __launch_bounds__(256) void logits_col_kernel()
{
    int j = blockIdx.x, h = blockIdx.y, b = blockIdx.z;
    __shared__ float qs[64][64];
    __shared__ float ks[64][64];
    size_t base = ((size_t)(b * DQKV + h * DHH)) * HWN + j * HH;
    int t = threadIdx.x;
    #pragma unroll
    for (int r = 0; r < 16; r++) {
        int idx = r * 256 + t;
        int d = idx >> 6, ii = idx & 63;
        qs[d][ii] = __half2float(g_QT[base + (size_t)d * HWN + ii]);
        ks[d][ii] = __half2float(g_KT[base + (size_t)d * HWN + ii]);
    }
    __syncthreads();
    int tx = t & 15, ty = t >> 4;
    u64 acc[4][2];
    #pragma unroll
    for (int u = 0; u < 4; u++) { acc[u][0] = 0ull; acc[u][1] = 0ull; }
    #pragma unroll
    for (int d = 0; d < 64; d++) {
        float4 q4 = *(float4*)&qs[d][ty * 4];
        const u64* kp = (const u64*)&ks[d][tx * 4];
        u64 k0 = kp[0], k1 = kp[1];
        u64 qa[4] = {pk2(q4.x), pk2(q4.y), pk2(q4.z), pk2(q4.w)};
        #pragma unroll
        for (int u = 0; u < 4; u++) {
            fma2(acc[u][0], qa[u], k0);
            fma2(acc[u][1], qa[u], k1);
        }
    }
    size_t pre = ((size_t)((b * NHH + h) * HH) * WW + j) * PLEN + 64;
    #pragma unroll
    for (int u = 0; u < 4; u++) {
        int i = ty * 4 + u;
        float2 p0 = up2(acc[u][0]), p1 = up2(acc[u][1]);
        sth4(&g_P[pre + (size_t)i * (WW * PLEN) + tx * 4],
             make_float4(p0.x * SCALE, p0.y * SCALE, p1.x * SCALE, p1.y * SCALE));
    }
}

// =====================================================================
// Kernel 5: softmax over 128 fp16 logits per query, in place.
// =====================================================================
__global__ __launch_bounds__(256) void softmax_kernel()
{
    size_t row = (size_t)blockIdx.x * 8 + (threadIdx.x >> 5);
    int lane = threadIdx.x & 31;
    __half* p = g_P + row * PLEN + lane * 4;
    float4 v = ldh4(p);
    float m = fmaxf(fmaxf(v.x, v.y), fmaxf(v.z, v.w));
    #pragma unroll
    for (int o = 16; o; o >>= 1) m = fmaxf(m, __shfl_xor_sync(0xffffffffu, m, o));
    v.x = __expf(v.x - m); v.y = __expf(v.y - m);
    v.z = __expf(v.z - m); v.w = __expf(v.w - m);
    float s = v.x + v.y + v.z + v.w;
    #pragma unroll
    for (int o = 16; o; o >>= 1) s += __shfl_xor_sync(0xffffffffu, s, o);
    float inv = 1.0f / s;
    v.x *= inv; v.y *= inv; v.z *= inv; v.w *= inv;
    sth4(p, v);
}

// =====================================================================
// Kernel 6: row attention (f32x2). fp16 in, fp16 out [b][p][ch].
// =====================================================================
__global__ __launch_bounds__(256) void attn_row_kernel()
{
    int i = blockIdx.x, h = blockIdx.y, b = blockIdx.z;
    __shared__ float vsT[64][68];
    __shared__ float psT[64][68];
    size_t vbase = ((size_t)(b * DQKV + h * DHH)) * HWN + i * WW;
    size_t pbase = (((size_t)((b * NHH + h) * HH + i)) * WW) * PLEN;
    int t = threadIdx.x;
    #pragma unroll
    for (int r = 0; r < 16; r++) {
        int idx = r * 256 + t;
        int a = idx >> 6, k = idx & 63;
        vsT[k][a] = __half2float(g_V[vbase + (size_t)a * HWN + k]);
        psT[k][a] = __half2float(g_P[pbase + (size_t)a * PLEN + k]);
    }
    __syncthreads();
    int tx = t & 15, ty = t >> 4;
    u64 acc[4][2];
    #pragma unroll
    for (int u = 0; u < 4; u++) { acc[u][0] = 0ull; acc[u][1] = 0ull; }
    #pragma unroll
    for (int k = 0; k < 64; k++) {
        float4 v4 = *(float4*)&vsT[k][ty * 4];
        const u64* pp = (const u64*)&psT[k][tx * 4];
        u64 p0 = pp[0], p1 = pp[1];
        u64 va[4] = {pk2(v4.x), pk2(v4.y), pk2(v4.z), pk2(v4.w)};
        #pragma unroll
        for (int u = 0; u < 4; u++) {
            fma2(acc[u][0], va[u], p0);
            fma2(acc[u][1], va[u], p1);
        }
    }
    float av[4][4];
    #pragma unroll
    for (int u = 0; u < 4; u++) {
        float2 a0 = up2(acc[u][0]), a1 = up2(acc[u][1]);
        av[u][0] = a0.x; av[u][1] = a0.y; av[u][2] = a1.x; av[u][3] = a1.y;
    }
    int chb = h * DHH + ty * 4;
    #pragma unroll
    for (int cc = 0; cc < 4; cc++) {
        int p = i * WW + tx * 4 + cc;
        sth4(g_A + ((size_t)b * HWN + p) * DQKV + chb,
             make_float4(av[0][cc], av[1][cc], av[2][cc], av[3][cc]));
    }
}

// =====================================================================
// Kernel 7: column attention (f32x2). fp16 in, fp16 out [b][p][ch].
// =====================================================================
__global__ __launch_bounds__(256) void attn_col_kernel()
{
    int j = blockIdx.x, h = blockIdx.y, b = blockIdx.z;
    __shared__ float vsT[64][68];
    __shared__ float psT[64][68];
    size_t vbase = ((size_t)(b * DQKV + h * DHH)) * HWN + j * HH;
    size_t pcol  = ((size_t)((b * NHH + h) * HH) * WW + j) * PLEN + 64;
    int t = threadIdx.x;
    #pragma unroll
    for (int r = 0; r < 16; r++) {
        int idx = r * 256 + t;
        int a = idx >> 6, k = idx & 63;
        vsT[k][a] = __half2float(g_VT[vbase + (size_t)a * HWN + k]);
        psT[k][a] = __half2float(g_P[pcol + (size_t)a * (WW * PLEN) + k]);
    }
    __syncthreads();
    int tx = t & 15, ty = t >> 4;
    u64 acc[4][2];
    #pragma unroll
    for (int u = 0; u < 4; u++) { acc[u][0] = 0ull; acc[u][1] = 0ull; }
    #pragma unroll
    for (int k = 0; k < 64; k++) {
        float4 v4 = *(float4*)&vsT[k][ty * 4];
        const u64* pp = (const u64*)&psT[k][tx * 4];
        u64 p0 = pp[0], p1 = pp[1];
        u64 va[4] = {pk2(v4.x), pk2(v4.y), pk2(v4.z), pk2(v4.w)};
        #pragma unroll
        for (int u = 0; u < 4; u++) {
            fma2(acc[u][0], va[u], p0);
            fma2(acc[u][1], va[u], p1);
        }
    }
    float av[4][4];
    #pragma unroll
    for (int u = 0; u < 4; u++) {
        float2 a0 = up2(acc[u][0]), a1 = up2(acc[u][1]);
        av[u][0] = a0.x; av[u][1] = a0.y; av[u][2] = a1.x; av[u][3] = a1.y;
    }
    int chb = h * DHH + ty * 4;
    #pragma unroll
    for (int cc = 0; cc < 4; cc++) {
        int p = (tx * 4 + cc) * WW + j;
        sth4(g_AT + ((size_t)b * HWN + p) * DQKV + chb,
             make_float4(av[0][cc], av[1][cc], av[2][cc], av[3][cc]));
    }
}

// =====================================================================
// Kernel 9: output projection + residual via mma.sync tf32.
// Reads fp16 A/AT, adds at fill; fp32 output.
// =====================================================================
__global__ __launch_bounds__(256, 2) void proj_mma(
    const float* __restrict__ x, const float* __restrict__ Wo,
    const float* __restrict__ bo, float* __restrict__ out)
{
    int pT = blockIdx.x, mT = blockIdx.y, b = blockIdx.z;
    int mOff = mT * 128;

    __shared__ uint32_t As[128][36];
    __shared__ uint32_t Bs[128][36];

    int t = threadIdx.x, lane = t & 31, wid = t >> 5;
    int g = lane >> 2, tig = lane & 3;
    int wm = (wid >> 2) * 64, wn = (wid & 3) * 32;

    const __half* a2w = g_A  + ((size_t)b * HWN + (size_t)pT * 128) * DQKV;
    const __half* a2h = g_AT + ((size_t)b * HWN + (size_t)pT * 128) * DQKV;

    float c[4][4][4];
    #pragma unroll
    for (int mi = 0; mi < 4; mi++)
        #pragma unroll
        for (int ni = 0; ni < 4; ni++)
            #pragma unroll
            for (int e = 0; e < 4; e++) c[mi][ni][e] = 0.0f;

    for (int c0 = 0; c0 < 16; c0++) {
        int kBase = c0 * 32;
        #pragma unroll
        for (int r = 0; r < 4; r++) {
            int idx = r * 256 + t;
            int row = idx >> 3, q = idx & 7;
            int k4 = kBase + q * 4;
            float4 va = *(const float4*)(Wo + (size_t)(mOff + row) * DQKV + k4);
            As[row][q * 4 + 0] = f2tf32(va.x);
            As[row][q * 4 + 1] = f2tf32(va.y);
            As[row][q * 4 + 2] = f2tf32(va.z);
            As[row][q * 4 + 3] = f2tf32(va.w);
            float4 vb = ldh4(a2w + (size_t)row * DQKV + k4);
            float4 vh = ldh4(a2h + (size_t)row * DQKV + k4);
            Bs[row][q * 4 + 0] = f2tf32(vb.x + vh.x);
            Bs[row][q * 4 + 1] = f2tf32(vb.y + vh.y);
            Bs[row][q * 4 + 2] = f2tf32(vb.z + vh.z);
            Bs[row][q * 4 + 3] = f2tf32(vb.w + vh.w);
        }
        __syncthreads();
        #pragma unroll
        for (int ks = 0; ks < 4; ks++) {
            int kk = ks * 8;
            uint32_t a[4][4], bfr[4][2];
            #pragma unroll
            for (int mi = 0; mi < 4; mi++) {
                int row = wm + mi * 16 + g;
                a[mi][0] = As[row][kk + tig];
                a[mi][1] = As[row + 8][kk + tig];
                a[mi][2] = As[row][kk + tig + 4];
                a[mi][3] = As[row + 8][kk + tig + 4];
            }
            #pragma unroll
            for (int ni = 0; ni < 4; ni++) {
                int col = wn + ni * 8 + g;
                bfr[ni][0] = Bs[col][kk + tig];
                bfr[ni][1] = Bs[col][kk + tig + 4];
            }
            #pragma unroll
            for (int mi = 0; mi < 4; mi++)
                #pragma unroll
                for (int ni = 0; ni < 4; ni++)
                    mma_tf32(c[mi][ni], a[mi], bfr[ni]);
        }
        __syncthreads();
    }

    #pragma unroll
    for (int mi = 0; mi < 4; mi++) {
        int row0 = wm + mi * 16 + g;
        int ch0 = mOff + row0;
        float bi0 = bo[ch0];
        float bi1 = bo[ch0 + 8];
        size_t base0 = ((size_t)b * CC + ch0) * HWN + (size_t)pT * 128;
        size_t base1 = base0 + (size_t)8 * HWN;
        #pragma unroll
        for (int ni = 0; ni < 4; ni++) {
            int col = wn + ni * 8 + tig * 2;
            float2 x0 = *(const float2*)(x + base0 + col);
            float2 x1 = *(const float2*)(x + base1 + col);
            float2 v0 = make_float2(c[mi][ni][0] + bi0 + x0.x,
                                    c[mi][ni][1] + bi0 + x0.y);
            float2 v1 = make_float2(c[mi][ni][2] + bi1 + x1.x,
                                    c[mi][ni][3] + bi1 + x1.y);
            *(float2*)(out + base0 + col) = v0;
            *(float2*)(out + base1 + col) = v1;
        }
    }
}

// =====================================================================
extern "C" void kernel_launch(void* const* d_in, const int* in_sizes, int n_in,
                              void* d_out, int out_size)
{
    const float* x   = (const float*)d_in[0];
    const float* pos = (const float*)d_in[1];
    const float* Wk  = (const float*)d_in[2];
    const float* bk  = (const float*)d_in[3];
    const float* Wq  = (const float*)d_in[4];
    const float* bq  = (const float*)d_in[5];
    const float* Wv  = (const float*)d_in[6];
    const float* bv  = (const float*)d_in[7];
    const float* Wo  = (const float*)d_in[8];
    const float* bo  = (const float*)d_in[9];
    float* out = (float*)d_out;

    xpose_x<<<dim3(64, 5, BB), 256>>>(x, pos);
    qkv_mma<<<dim3(32, 12, BB), 256>>>(Wq, bq, Wk, bk, Wv, bv);
    transpose3_kernel<<<dim3(BB * DQKV, 3), 256>>>();
    logits_row_kernel<<<dim3(HH, NHH, BB), 256>>>();
    logits_col_kernel<<<dim3(WW, NHH, BB), 256>>>();
    softmax_kernel<<<65536, 256>>>();
    attn_row_kernel<<<dim3(HH, NHH, BB), 256>>>();
    attn_col_kernel<<<dim3(WW, NHH, BB), 256>>>();
    proj_mma<<<dim3(32, 2, BB), 256>>>(x, Wo, bo, out);
}

// round 15
// speedup vs baseline: 1.2712x; 1.1287x over previous
#include <cuda_runtime.h>
#include <cuda_fp16.h>
#include <cstdint>

// ---------------- problem constants ----------------
#define BB   16
#define CC   256
#define HH   64
#define WW   64
#define NHH  8
#define DHH  64
#define CIN  260
#define KPAD 264
#define DQKV 512
#define HWN  4096
#define PLEN 128
#define SCALE 0.08838834764831843f  // 1/sqrt(128)

typedef unsigned long long u64;

// ---------------- tf32 helpers ----------------
__device__ __forceinline__ uint32_t f2tf32(float f) {
    uint32_t u;
    asm("cvt.rna.tf32.f32 %0, %1;" : "=r"(u) : "f"(f));
    return u;
}
__device__ __forceinline__ void mma_tf32(float c[4], const uint32_t a[4],
                                         const uint32_t bfr[2]) {
    asm volatile(
        "mma.sync.aligned.m16n8k8.row.col.f32.tf32.tf32.f32 "
        "{%0,%1,%2,%3}, {%4,%5,%6,%7}, {%8,%9}, {%0,%1,%2,%3};"
        : "+f"(c[0]), "+f"(c[1]), "+f"(c[2]), "+f"(c[3])
        : "r"(a[0]), "r"(a[1]), "r"(a[2]), "r"(a[3]),
          "r"(bfr[0]), "r"(bfr[1]));
}

// ---------------- fp16 HMMA helper (m16n8k16, fp32 accum) ----------------
__device__ __forceinline__ void mma_f16(float c[4], const uint32_t a[4],
                                        const uint32_t bfr[2]) {
    asm volatile(
        "mma.sync.aligned.m16n8k16.row.col.f32.f16.f16.f32 "
        "{%0,%1,%2,%3}, {%4,%5,%6,%7}, {%8,%9}, {%0,%1,%2,%3};"
        : "+f"(c[0]), "+f"(c[1]), "+f"(c[2]), "+f"(c[3])
        : "r"(a[0]), "r"(a[1]), "r"(a[2]), "r"(a[3]),
          "r"(bfr[0]), "r"(bfr[1]));
}

// ---------------- fp16 pack/unpack helpers ----------------
__device__ __forceinline__ float4 ldh4(const __half* p) {
    uint2 u = *(const uint2*)p;
    __half2 h0 = *(__half2*)&u.x, h1 = *(__half2*)&u.y;
    float2 f0 = __half22float2(h0), f1 = __half22float2(h1);
    return make_float4(f0.x, f0.y, f1.x, f1.y);
}
__device__ __forceinline__ void sth4(__half* p, float4 v) {
    uint2 u;
    *(__half2*)&u.x = __floats2half2_rn(v.x, v.y);
    *(__half2*)&u.y = __floats2half2_rn(v.z, v.w);
    *(uint2*)p = u;
}
__device__ __forceinline__ uint32_t packh2(__half a, __half b) {
    __half2 h = __halves2half2(a, b);
    return *(uint32_t*)&h;
}

// ---------------- device scratch (all fp16) ----------------
#define TSZ ((size_t)BB * DQKV * HWN)
__device__ __half g_Q [TSZ];
__device__ __half g_K [TSZ];
__device__ __half g_V [TSZ];
__device__ __half g_QT[TSZ];
__device__ __half g_KT[TSZ];
__device__ __half g_VT[TSZ];
__device__ __half g_A [TSZ];    // a_w in [b][p][ch]
__device__ __half g_AT[TSZ];    // a_h in [b][p][ch]
__device__ __half g_P [(size_t)BB * NHH * HH * WW * PLEN];
__device__ __half g_XT[(size_t)BB * HWN * KPAD];

// =====================================================================
// Kernel 0: transpose xp = concat(x,pos) -> g_XT [b][p][264] (fp16)
// =====================================================================
__global__ __launch_bounds__(256) void xpose_x(
    const float* __restrict__ x, const float* __restrict__ pos)
{
    __shared__ float tile[64][65];
    int t = threadIdx.x;
    int p0 = blockIdx.x * 64, c0 = blockIdx.y * 64, b = blockIdx.z;
    #pragma unroll
    for (int r = 0; r < 16; r++) {
        int idx = r * 256 + t;
        int cc = idx >> 6, pp = idx & 63;
        int c = c0 + cc;
        float v = 0.0f;
        if (c < CC)       v = x[((size_t)b * CC + c) * HWN + p0 + pp];
        else if (c < CIN) v = pos[(size_t)(c - CC) * HWN + p0 + pp];
        tile[cc][pp] = v;
    }
    __syncthreads();
    #pragma unroll
    for (int r = 0; r < 16; r++) {
        int idx = r * 256 + t;
        int pp = idx >> 6, cc = idx & 63;
        int c = c0 + cc;
        if (c < KPAD)
            g_XT[((size_t)b * HWN + p0 + pp) * KPAD + c] = __float2half(tile[cc][pp]);
    }
}

// =====================================================================
// Kernel 1: QKV projection via mma.sync tf32; fp16 in (XT) / fp16 out.
// =====================================================================
__global__ __launch_bounds__(256, 2) void qkv_mma(
    const float* __restrict__ Wq, const float* __restrict__ bq,
    const float* __restrict__ Wk, const float* __restrict__ bk,
    const float* __restrict__ Wv, const float* __restrict__ bv)
{
    int pT = blockIdx.x, nT = blockIdx.y, b = blockIdx.z;
    int which = nT >> 2;
    int mOff  = (nT & 3) * 128;
    const float* Wt   = (which == 0) ? Wq : (which == 1) ? Wk : Wv;
    const float* bias = (which == 0) ? bq : (which == 1) ? bk : bv;
    __half*      outp = (which == 0) ? g_Q : (which == 1) ? g_K : g_V;

    __shared__ uint32_t As[128][36];
    __shared__ uint32_t Bs[128][36];

    int t = threadIdx.x, lane = t & 31, wid = t >> 5;
    int g = lane >> 2, tig = lane & 3;
    int wm = (wid >> 2) * 64, wn = (wid & 3) * 32;

    const __half* xt = g_XT + ((size_t)b * HWN + (size_t)pT * 128) * KPAD;

    float c[4][4][4];
    #pragma unroll
    for (int mi = 0; mi < 4; mi++)
        #pragma unroll
        for (int ni = 0; ni < 4; ni++)
            #pragma unroll
            for (int e = 0; e < 4; e++) c[mi][ni][e] = 0.0f;

    for (int c0 = 0; c0 < 9; c0++) {
        int kBase = c0 * 32;
        #pragma unroll
        for (int r = 0; r < 4; r++) {
            int idx = r * 256 + t;
            int row = idx >> 3, q = idx & 7;
            int k4 = kBase + q * 4;
            float4 va = make_float4(0.f, 0.f, 0.f, 0.f);
            if (k4 <= CIN - 4)
                va = *(const float4*)(Wt + (size_t)(mOff + row) * CIN + k4);
            As[row][q * 4 + 0] = f2tf32(va.x);
            As[row][q * 4 + 1] = f2tf32(va.y);
            As[row][q * 4 + 2] = f2tf32(va.z);
            As[row][q * 4 + 3] = f2tf32(va.w);
            float4 vb = make_float4(0.f, 0.f, 0.f, 0.f);
            if (k4 <= KPAD - 4)
                vb = ldh4(xt + (size_t)row * KPAD + k4);
            Bs[row][q * 4 + 0] = f2tf32(vb.x);
            Bs[row][q * 4 + 1] = f2tf32(vb.y);
            Bs[row][q * 4 + 2] = f2tf32(vb.z);
            Bs[row][q * 4 + 3] = f2tf32(vb.w);
        }
        __syncthreads();
        #pragma unroll
        for (int ks = 0; ks < 4; ks++) {
            int kk = ks * 8;
            uint32_t a[4][4], bfr[4][2];
            #pragma unroll
            for (int mi = 0; mi < 4; mi++) {
                int row = wm + mi * 16 + g;
                a[mi][0] = As[row][kk + tig];
                a[mi][1] = As[row + 8][kk + tig];
                a[mi][2] = As[row][kk + tig + 4];
                a[mi][3] = As[row + 8][kk + tig + 4];
            }
            #pragma unroll
            for (int ni = 0; ni < 4; ni++) {
                int col = wn + ni * 8 + g;
                bfr[ni][0] = Bs[col][kk + tig];
                bfr[ni][1] = Bs[col][kk + tig + 4];
            }
            #pragma unroll
            for (int mi = 0; mi < 4; mi++)
                #pragma unroll
                for (int ni = 0; ni < 4; ni++)
                    mma_tf32(c[mi][ni], a[mi], bfr[ni]);
        }
        __syncthreads();
    }

    #pragma unroll
    for (int mi = 0; mi < 4; mi++) {
        int row0 = wm + mi * 16 + g;
        float bi0 = bias[mOff + row0];
        float bi1 = bias[mOff + row0 + 8];
        __half* o0 = outp + ((size_t)b * DQKV + mOff + row0) * HWN + (size_t)pT * 128;
        __half* o1 = o0 + (size_t)8 * HWN;
        #pragma unroll
        for (int ni = 0; ni < 4; ni++) {
            int col = wn + ni * 8 + tig * 2;
            *(__half2*)(o0 + col) = __floats2half2_rn(c[mi][ni][0] + bi0,
                                                      c[mi][ni][1] + bi0);
            *(__half2*)(o1 + col) = __floats2half2_rn(c[mi][ni][2] + bi1,
                                                      c[mi][ni][3] + bi1);
        }
    }
}

// =====================================================================
// Kernel 2: transpose each 64x64 image of Q,K,V -> QT,KT,VT (fp16)
// =====================================================================
__global__ __launch_bounds__(256) void transpose3_kernel()
{
    const __half* src = (blockIdx.y == 0) ? g_Q : (blockIdx.y == 1) ? g_K : g_V;
    __half*       dst = (blockIdx.y == 0) ? g_QT : (blockIdx.y == 1) ? g_KT : g_VT;
    size_t base = (size_t)blockIdx.x * HWN;
    __shared__ __half sm[64][65];
    int t = threadIdx.x;
    #pragma unroll
    for (int r = 0; r < 16; r++) {
        int idx = r * 256 + t;
        sm[idx >> 6][idx & 63] = src[base + idx];
    }
    __syncthreads();
    #pragma unroll
    for (int r = 0; r < 16; r++) {
        int idx = r * 256 + t;
        dst[base + idx] = sm[idx & 63][idx >> 6];
    }
}

// =====================================================================
// Logits HMMA core: S[m][n] = sum_d A[d][m]*B[d][n], 64x64x64.
// qg/kg point to [d][x] rows (stride HWN). Output fp16 at
// outp + m*mStride + n (scaled).
// =====================================================================
__device__ __forceinline__ void logits_hmma(
    const __half* __restrict__ qg, const __half* __restrict__ kg_,
    __half* __restrict__ outp, size_t mStride)
{
    __shared__ uint32_t As[64][33];   // As[m][d2] = {q[2d2][m], q[2d2+1][m]}
    __shared__ uint32_t Bs[64][33];
    int t = threadIdx.x;
    #pragma unroll
    for (int r = 0; r < 8; r++) {
        int idx = r * 256 + t;
        int d2 = idx >> 6, x = idx & 63;
        size_t o0 = (size_t)(2 * d2) * HWN + x;
        As[x][d2] = packh2(qg[o0], qg[o0 + HWN]);
        Bs[x][d2] = packh2(kg_[o0], kg_[o0 + HWN]);
    }
    __syncthreads();
    int lane = t & 31, wid = t >> 5;
    int g = lane >> 2, tg = lane & 3;
    int wm = (wid >> 2) * 32, wn = (wid & 3) * 16;

    float c[2][2][4];
    #pragma unroll
    for (int mi = 0; mi < 2; mi++)
        #pragma unroll
        for (int ni = 0; ni < 2; ni++)
            #pragma unroll
            for (int e = 0; e < 4; e++) c[mi][ni][e] = 0.0f;

    #pragma unroll
    for (int ks = 0; ks < 4; ks++) {
        int k2 = ks * 8;
        uint32_t a[2][4], bb[2][2];
        #pragma unroll
        for (int mi = 0; mi < 2; mi++) {
            int row = wm + mi * 16 + g;
            a[mi][0] = As[row][k2 + tg];
            a[mi][1] = As[row + 8][k2 + tg];
            a[mi][2] = As[row][k2 + 4 + tg];
            a[mi][3] = As[row + 8][k2 + 4 + tg];
        }
        #pragma unroll
        for (int ni = 0; ni < 2; ni++) {
            int col = wn + ni * 8 + g;
            bb[ni][0] = Bs[col][k2 + tg];
            bb[ni][1] = Bs[col][k2 + 4 + tg];
        }
        #pragma unroll
        for (int mi = 0; mi < 2; mi++)
            #pragma unroll
            for (int ni = 0; ni < 2; ni++)
                mma_f16(c[mi][ni], a[mi], bb[ni]);
    }

    #pragma unroll
    for (int mi = 0; mi < 2; mi++) {
        int m0 = wm + mi * 16 + g;
        #pragma unroll
        for (int ni = 0; ni < 2; ni++) {
            int n = wn + ni * 8 + tg * 2;
            *(__half2*)(outp + (size_t)m0 * mStride + n) =
                __floats2half2_rn(c[mi][ni][0] * SCALE, c[mi][ni][1] * SCALE);
            *(__half2*)(outp + (size_t)(m0 + 8) * mStride + n) =
                __floats2half2_rn(c[mi][ni][2] * SCALE, c[mi][ni][3] * SCALE);
        }
    }
}

// Kernel 3: row logits. block (i, h, b).
__global__ __launch_bounds__(256) void logits_row_kernel()
{
    int i = blockIdx.x, h = blockIdx.y, b = blockIdx.z;
    size_t base  = ((size_t)(b * DQKV + h * DHH)) * HWN + i * WW;
    size_t pbase = (((size_t)((b * NHH + h) * HH + i)) * WW) * PLEN;
    logits_hmma(g_Q + base, g_K + base, g_P + pbase, PLEN);
}

// Kernel 4: column logits. block (j, h, b).
__global__ __launch_bounds__(256) void logits_col_kernel()
{
    int j = blockIdx.x, h = blockIdx.y, b = blockIdx.z;
    size_t base = ((size_t)(b * DQKV + h * DHH)) * HWN + j * HH;
    size_t pre  = ((size_t)((b * NHH + h) * HH) * WW + j) * PLEN + 64;
    logits_hmma(g_QT + base, g_KT + base, g_P + pre, (size_t)WW * PLEN);
}

// =====================================================================
// Kernel 5: softmax over 128 fp16 logits per query, in place.
// =====================================================================
__global__ __launch_bounds__(256) void softmax_kernel()
{
    size_t row = (size_t)blockIdx.x * 8 + (threadIdx.x >> 5);
    int lane = threadIdx.x & 31;
    __half* p = g_P + row * PLEN + lane * 4;
    float4 v = ldh4(p);
    float m = fmaxf(fmaxf(v.x, v.y), fmaxf(v.z, v.w));
    #pragma unroll
    for (int o = 16; o; o >>= 1) m = fmaxf(m, __shfl_xor_sync(0xffffffffu, m, o));
    v.x = __expf(v.x - m); v.y = __expf(v.y - m);
    v.z = __expf(v.z - m); v.w = __expf(v.w - m);
    float s = v.x + v.y + v.z + v.w;
    #pragma unroll
    for (int o = 16; o; o >>= 1) s += __shfl_xor_sync(0xffffffffu, s, o);
    float inv = 1.0f / s;
    v.x *= inv; v.y *= inv; v.z *= inv; v.w *= inv;
    sth4(p, v);
}

// =====================================================================
// Attention HMMA core: out[d][q] = sum_k V[d][k]*P[q][k], 64x64x64.
// vg rows [d][k] (stride HWN); pg rows [q][k] (stride pStride).
// Result staged to os[d][q], then stored half4-per-4ch to [p][ch].
// =====================================================================
__device__ __forceinline__ void attn_hmma(
    const __half* __restrict__ vg, const __half* __restrict__ pg,
    size_t pStride, __half os[64][66])
{
    __shared__ uint32_t As[64][33];   // V: As[d][k2]
    __shared__ uint32_t Bs[64][33];   // P: Bs[q][k2]
    int t = threadIdx.x;
    #pragma unroll
    for (int r = 0; r < 8; r++) {
        int idx = r * 256 + t;
        int row = idx >> 5, k2 = idx & 31;
        As[row][k2] = *(const uint32_t*)(vg + (size_t)row * HWN + 2 * k2);
        Bs[row][k2] = *(const uint32_t*)(pg + (size_t)row * pStride + 2 * k2);
    }
    __syncthreads();
    int lane = t & 31, wid = t >> 5;
    int g = lane >> 2, tg = lane & 3;
    int wm = (wid >> 2) * 32, wn = (wid & 3) * 16;

    float c[2][2][4];
    #pragma unroll
    for (int mi = 0; mi < 2; mi++)
        #pragma unroll
        for (int ni = 0; ni < 2; ni++)
            #pragma unroll
            for (int e = 0; e < 4; e++) c[mi][ni][e] = 0.0f;

    #pragma unroll
    for (int ks = 0; ks < 4; ks++) {
        int k2 = ks * 8;
        uint32_t a[2][4], bb[2][2];
        #pragma unroll
        for (int mi = 0; mi < 2; mi++) {
            int row = wm + mi * 16 + g;
            a[mi][0] = As[row][k2 + tg];
            a[mi][1] = As[row + 8][k2 + tg];
            a[mi][2] = As[row][k2 + 4 + tg];
            a[mi][3] = As[row + 8][k2 + 4 + tg];
        }
        #pragma unroll
        for (int ni = 0; ni < 2; ni++) {
            int col = wn + ni * 8 + g;
            bb[ni][0] = Bs[col][k2 + tg];
            bb[ni][1] = Bs[col][k2 + 4 + tg];
        }
        #pragma unroll
        for (int mi = 0; mi < 2; mi++)
            #pragma unroll
            for (int ni = 0; ni < 2; ni++)
                mma_f16(c[mi][ni], a[mi], bb[ni]);
    }

    // stage to os[d][q]
    #pragma unroll
    for (int mi = 0; mi < 2; mi++) {
        int d0 = wm + mi * 16 + g;
        #pragma unroll
        for (int ni = 0; ni < 2; ni++) {
            int q = wn + ni * 8 + tg * 2;
            *(__half2*)&os[d0][q]     = __floats2half2_rn(c[mi][ni][0], c[mi][ni][1]);
            *(__half2*)&os[d0 + 8][q] = __floats2half2_rn(c[mi][ni][2], c[mi][ni][3]);
        }
    }
    __syncthreads();
}

// Kernel 6: row attention. block (i,h,b). out -> g_A [b][p][ch]
__global__ __launch_bounds__(256) void attn_row_kernel()
{
    int i = blockIdx.x, h = blockIdx.y, b = blockIdx.z;
    __shared__ __half os[64][66];
    size_t vbase = ((size_t)(b * DQKV + h * DHH)) * HWN + i * WW;
    size_t pbase = (((size_t)((b * NHH + h) * HH + i)) * WW) * PLEN;
    attn_hmma(g_V + vbase, g_P + pbase, PLEN, os);
    int t = threadIdx.x;
    int ty = t >> 4, tx = t & 15;
    int chb = h * DHH + ty * 4;
    #pragma unroll
    for (int cc = 0; cc < 4; cc++) {
        int q = tx * 4 + cc;
        int p = i * WW + q;
        uint2 u;
        *(__half2*)&u.x = __halves2half2(os[ty * 4 + 0][q], os[ty * 4 + 1][q]);
        *(__half2*)&u.y = __halves2half2(os[ty * 4 + 2][q], os[ty * 4 + 3][q]);
        *(uint2*)(g_A + ((size_t)b * HWN + p) * DQKV + chb) = u;
    }
}

// Kernel 7: column attention. block (j,h,b). out -> g_AT [b][p][ch]
__global__ __launch_bounds__(256) void attn_col_kernel()
{
    int j = blockIdx.x, h = blockIdx.y, b = blockIdx.z;
    __shared__ __half os[64][66];
    size_t vbase = ((size_t)(b * DQKV + h * DHH)) * HWN + j * HH;
    size_t pcol  = ((size_t)((b * NHH + h) * HH) * WW + j) * PLEN + 64;
    attn_hmma(g_VT + vbase, g_P + pcol, (size_t)WW * PLEN, os);
    int t = threadIdx.x;
    int ty = t >> 4, tx = t & 15;
    int chb = h * DHH + ty * 4;
    #pragma unroll
    for (int cc = 0; cc < 4; cc++) {
        int q = tx * 4 + cc;           // q = i
        int p = q * WW + j;
        uint2 u;
        *(__half2*)&u.x = __halves2half2(os[ty * 4 + 0][q], os[ty * 4 + 1][q]);
        *(__half2*)&u.y = __halves2half2(os[ty * 4 + 2][q], os[ty * 4 + 3][q]);
        *(uint2*)(g_AT + ((size_t)b * HWN + p) * DQKV + chb) = u;
    }
}

// =====================================================================
// Kernel 9: output projection + residual via mma.sync tf32.
// =====================================================================
__global__ __launch_bounds__(256, 2) void proj_mma(
    const float* __restrict__ x, const float* __restrict__ Wo,
    const float* __restrict__ bo, float* __restrict__ out)
{
    int pT = blockIdx.x, mT = blockIdx.y, b = blockIdx.z;
    int mOff = mT * 128;

    __shared__ uint32_t As[128][36];
    __shared__ uint32_t Bs[128][36];

    int t = threadIdx.x, lane = t & 31, wid = t >> 5;
    int g = lane >> 2, tig = lane & 3;
    int wm = (wid >> 2) * 64, wn = (wid & 3) * 32;

    const __half* a2w = g_A  + ((size_t)b * HWN + (size_t)pT * 128) * DQKV;
    const __half* a2h = g_AT + ((size_t)b * HWN + (size_t)pT * 128) * DQKV;

    float c[4][4][4];
    #pragma unroll
    for (int mi = 0; mi < 4; mi++)
        #pragma unroll
        for (int ni = 0; ni < 4; ni++)
            #pragma unroll
            for (int e = 0; e < 4; e++) c[mi][ni][e] = 0.0f;

    for (int c0 = 0; c0 < 16; c0++) {
        int kBase = c0 * 32;
        #pragma unroll
        for (int r = 0; r < 4; r++) {
            int idx = r * 256 + t;
            int row = idx >> 3, q = idx & 7;
            int k4 = kBase + q * 4;
            float4 va = *(const float4*)(Wo + (size_t)(mOff + row) * DQKV + k4);
            As[row][q * 4 + 0] = f2tf32(va.x);
            As[row][q * 4 + 1] = f2tf32(va.y);
            As[row][q * 4 + 2] = f2tf32(va.z);
            As[row][q * 4 + 3] = f2tf32(va.w);
            float4 vb = ldh4(a2w + (size_t)row * DQKV + k4);
            float4 vh = ldh4(a2h + (size_t)row * DQKV + k4);
            Bs[row][q * 4 + 0] = f2tf32(vb.x + vh.x);
            Bs[row][q * 4 + 1] = f2tf32(vb.y + vh.y);
            Bs[row][q * 4 + 2] = f2tf32(vb.z + vh.z);
            Bs[row][q * 4 + 3] = f2tf32(vb.w + vh.w);
        }
        __syncthreads();
        #pragma unroll
        for (int ks = 0; ks < 4; ks++) {
            int kk = ks * 8;
            uint32_t a[4][4], bfr[4][2];
            #pragma unroll
            for (int mi = 0; mi < 4; mi++) {
                int row = wm + mi * 16 + g;
                a[mi][0] = As[row][kk + tig];
                a[mi][1] = As[row + 8][kk + tig];
                a[mi][2] = As[row][kk + tig + 4];
                a[mi][3] = As[row + 8][kk + tig + 4];
            }
            #pragma unroll
            for (int ni = 0; ni < 4; ni++) {
                int col = wn + ni * 8 + g;
                bfr[ni][0] = Bs[col][kk + tig];
                bfr[ni][1] = Bs[col][kk + tig + 4];
            }
            #pragma unroll
            for (int mi = 0; mi < 4; mi++)
                #pragma unroll
                for (int ni = 0; ni < 4; ni++)
                    mma_tf32(c[mi][ni], a[mi], bfr[ni]);
        }
        __syncthreads();
    }

    #pragma unroll
    for (int mi = 0; mi < 4; mi++) {
        int row0 = wm + mi * 16 + g;
        int ch0 = mOff + row0;
        float bi0 = bo[ch0];
        float bi1 = bo[ch0 + 8];
        size_t base0 = ((size_t)b * CC + ch0) * HWN + (size_t)pT * 128;
        size_t base1 = base0 + (size_t)8 * HWN;
        #pragma unroll
        for (int ni = 0; ni < 4; ni++) {
            int col = wn + ni * 8 + tig * 2;
            float2 x0 = *(const float2*)(x + base0 + col);
            float2 x1 = *(const float2*)(x + base1 + col);
            float2 v0 = make_float2(c[mi][ni][0] + bi0 + x0.x,
                                    c[mi][ni][1] + bi0 + x0.y);
            float2 v1 = make_float2(c[mi][ni][2] + bi1 + x1.x,
                                    c[mi][ni][3] + bi1 + x1.y);
            *(float2*)(out + base0 + col) = v0;
            *(float2*)(out + base1 + col) = v1;
        }
    }
}

// =====================================================================
extern "C" void kernel_launch(void* const* d_in, const int* in_sizes, int n_in,
                              void* d_out, int out_size)
{
    const float* x   = (const float*)d_in[0];
    const float* pos = (const float*)d_in[1];
    const float* Wk  = (const float*)d_in[2];
    const float* bk  = (const float*)d_in[3];
    const float* Wq  = (const float*)d_in[4];
    const float* bq  = (const float*)d_in[5];
    const float* Wv  = (const float*)d_in[6];
    const float* bv  = (const float*)d_in[7];
    const float* Wo  = (const float*)d_in[8];
    const float* bo  = (const float*)d_in[9];
    float* out = (float*)d_out;

    xpose_x<<<dim3(64, 5, BB), 256>>>(x, pos);
    qkv_mma<<<dim3(32, 12, BB), 256>>>(Wq, bq, Wk, bk, Wv, bv);
    transpose3_kernel<<<dim3(BB * DQKV, 3), 256>>>();
    logits_row_kernel<<<dim3(HH, NHH, BB), 256>>>();
    logits_col_kernel<<<dim3(WW, NHH, BB), 256>>>();
    softmax_kernel<<<65536, 256>>>();
    attn_row_kernel<<<dim3(HH, NHH, BB), 256>>>();
    attn_col_kernel<<<dim3(WW, NHH, BB), 256>>>();
    proj_mma<<<dim3(32, 2, BB), 256>>>(x, Wo, bo, out);
}

// round 17
// speedup vs baseline: 1.4540x; 1.1437x over previous
#include <cuda_runtime.h>
#include <cuda_fp16.h>
#include <cstdint>

// ---------------- problem constants ----------------
#define BB   16
#define CC   256
#define HH   64
#define WW   64
#define NHH  8
#define DHH  64
#define CIN  260
#define KPAD 264
#define DQKV 512
#define HWN  4096
#define PLEN 128
#define SCALE 0.08838834764831843f  // 1/sqrt(128)

typedef unsigned long long u64;

// ---------------- fp16 HMMA helper (m16n8k16, fp32 accum) ----------------
__device__ __forceinline__ void mma_f16(float c[4], const uint32_t a[4],
                                        const uint32_t bfr[2]) {
    asm volatile(
        "mma.sync.aligned.m16n8k16.row.col.f32.f16.f16.f32 "
        "{%0,%1,%2,%3}, {%4,%5,%6,%7}, {%8,%9}, {%0,%1,%2,%3};"
        : "+f"(c[0]), "+f"(c[1]), "+f"(c[2]), "+f"(c[3])
        : "r"(a[0]), "r"(a[1]), "r"(a[2]), "r"(a[3]),
          "r"(bfr[0]), "r"(bfr[1]));
}

// ---------------- fp16 pack/unpack helpers ----------------
__device__ __forceinline__ float4 ldh4(const __half* p) {
    uint2 u = *(const uint2*)p;
    __half2 h0 = *(__half2*)&u.x, h1 = *(__half2*)&u.y;
    float2 f0 = __half22float2(h0), f1 = __half22float2(h1);
    return make_float4(f0.x, f0.y, f1.x, f1.y);
}
__device__ __forceinline__ void sth4(__half* p, float4 v) {
    uint2 u;
    *(__half2*)&u.x = __floats2half2_rn(v.x, v.y);
    *(__half2*)&u.y = __floats2half2_rn(v.z, v.w);
    *(uint2*)p = u;
}
__device__ __forceinline__ uint32_t packh2(__half a, __half b) {
    __half2 h = __halves2half2(a, b);
    return *(uint32_t*)&h;
}
__device__ __forceinline__ uint32_t packf2h(float a, float b) {
    __half2 h = __floats2half2_rn(a, b);
    return *(uint32_t*)&h;
}

// ---------------- device scratch (all fp16) ----------------
#define TSZ ((size_t)BB * DQKV * HWN)
__device__ __half g_Q [TSZ];
__device__ __half g_K [TSZ];
__device__ __half g_V [TSZ];
__device__ __half g_QT[TSZ];
__device__ __half g_KT[TSZ];
__device__ __half g_VT[TSZ];
__device__ __half g_A [TSZ];    // a_w in [b][p][ch]
__device__ __half g_AT[TSZ];    // a_h in [b][p][ch]
__device__ __half g_P [(size_t)BB * NHH * HH * WW * PLEN];
__device__ __half g_XT[(size_t)BB * HWN * KPAD];

// =====================================================================
// Kernel 0: transpose xp = concat(x,pos) -> g_XT [b][p][264] (fp16)
// =====================================================================
__global__ __launch_bounds__(256) void xpose_x(
    const float* __restrict__ x, const float* __restrict__ pos)
{
    __shared__ float tile[64][65];
    int t = threadIdx.x;
    int p0 = blockIdx.x * 64, c0 = blockIdx.y * 64, b = blockIdx.z;
    #pragma unroll
    for (int r = 0; r < 16; r++) {
        int idx = r * 256 + t;
        int cc = idx >> 6, pp = idx & 63;
        int c = c0 + cc;
        float v = 0.0f;
        if (c < CC)       v = x[((size_t)b * CC + c) * HWN + p0 + pp];
        else if (c < CIN) v = pos[(size_t)(c - CC) * HWN + p0 + pp];
        tile[cc][pp] = v;
    }
    __syncthreads();
    #pragma unroll
    for (int r = 0; r < 16; r++) {
        int idx = r * 256 + t;
        int pp = idx >> 6, cc = idx & 63;
        int c = c0 + cc;
        if (c < KPAD)
            g_XT[((size_t)b * HWN + p0 + pp) * KPAD + c] = __float2half(tile[cc][pp]);
    }
}

// =====================================================================
// Kernel 1: QKV projection via fp16 HMMA m16n8k16.
// Block: 128 ch x 128 p; K chunks of 32 (16 half2, pad 20).
// =====================================================================
__global__ __launch_bounds__(256, 2) void qkv_mma(
    const float* __restrict__ Wq, const float* __restrict__ bq,
    const float* __restrict__ Wk, const float* __restrict__ bk,
    const float* __restrict__ Wv, const float* __restrict__ bv)
{
    int pT = blockIdx.x, nT = blockIdx.y, b = blockIdx.z;
    int which = nT >> 2;
    int mOff  = (nT & 3) * 128;
    const float* Wt   = (which == 0) ? Wq : (which == 1) ? Wk : Wv;
    const float* bias = (which == 0) ? bq : (which == 1) ? bk : bv;
    __half*      outp = (which == 0) ? g_Q : (which == 1) ? g_K : g_V;

    __shared__ uint32_t As[128][20];   // W rows, half2-packed
    __shared__ uint32_t Bs[128][20];   // XT rows, half2-packed

    int t = threadIdx.x, lane = t & 31, wid = t >> 5;
    int g = lane >> 2, tig = lane & 3;
    int wm = (wid >> 2) * 64, wn = (wid & 3) * 32;

    const __half* xt = g_XT + ((size_t)b * HWN + (size_t)pT * 128) * KPAD;

    float c[4][4][4];
    #pragma unroll
    for (int mi = 0; mi < 4; mi++)
        #pragma unroll
        for (int ni = 0; ni < 4; ni++)
            #pragma unroll
            for (int e = 0; e < 4; e++) c[mi][ni][e] = 0.0f;

    for (int c0 = 0; c0 < 9; c0++) {
        int kBase = c0 * 32;
        #pragma unroll
        for (int r = 0; r < 4; r++) {
            int idx = r * 256 + t;
            int row = idx >> 3, q = idx & 7;
            int k4 = kBase + q * 4;
            float4 va = make_float4(0.f, 0.f, 0.f, 0.f);
            if (k4 <= CIN - 4)
                va = *(const float4*)(Wt + (size_t)(mOff + row) * CIN + k4);
            As[row][q * 2]     = packf2h(va.x, va.y);
            As[row][q * 2 + 1] = packf2h(va.z, va.w);
            uint2 vb = make_uint2(0u, 0u);
            if (k4 <= KPAD - 4)
                vb = *(const uint2*)(xt + (size_t)row * KPAD + k4);
            Bs[row][q * 2]     = vb.x;
            Bs[row][q * 2 + 1] = vb.y;
        }
        __syncthreads();
        #pragma unroll
        for (int ks = 0; ks < 2; ks++) {
            int kk = ks * 8;
            uint32_t a[4][4], bfr[4][2];
            #pragma unroll
            for (int mi = 0; mi < 4; mi++) {
                int row = wm + mi * 16 + g;
                a[mi][0] = As[row][kk + tig];
                a[mi][1] = As[row + 8][kk + tig];
                a[mi][2] = As[row][kk + tig + 4];
                a[mi][3] = As[row + 8][kk + tig + 4];
            }
            #pragma unroll
            for (int ni = 0; ni < 4; ni++) {
                int col = wn + ni * 8 + g;
                bfr[ni][0] = Bs[col][kk + tig];
                bfr[ni][1] = Bs[col][kk + tig + 4];
            }
            #pragma unroll
            for (int mi = 0; mi < 4; mi++)
                #pragma unroll
                for (int ni = 0; ni < 4; ni++)
                    mma_f16(c[mi][ni], a[mi], bfr[ni]);
        }
        __syncthreads();
    }

    #pragma unroll
    for (int mi = 0; mi < 4; mi++) {
        int row0 = wm + mi * 16 + g;
        float bi0 = bias[mOff + row0];
        float bi1 = bias[mOff + row0 + 8];
        __half* o0 = outp + ((size_t)b * DQKV + mOff + row0) * HWN + (size_t)pT * 128;
        __half* o1 = o0 + (size_t)8 * HWN;
        #pragma unroll
        for (int ni = 0; ni < 4; ni++) {
            int col = wn + ni * 8 + tig * 2;
            *(__half2*)(o0 + col) = __floats2half2_rn(c[mi][ni][0] + bi0,
                                                      c[mi][ni][1] + bi0);
            *(__half2*)(o1 + col) = __floats2half2_rn(c[mi][ni][2] + bi1,
                                                      c[mi][ni][3] + bi1);
        }
    }
}

// =====================================================================
// Kernel 2: transpose each 64x64 image of Q,K,V -> QT,KT,VT (fp16)
// =====================================================================
__global__ __launch_bounds__(256) void transpose3_kernel()
{
    const __half* src = (blockIdx.y == 0) ? g_Q : (blockIdx.y == 1) ? g_K : g_V;
    __half*       dst = (blockIdx.y == 0) ? g_QT : (blockIdx.y == 1) ? g_KT : g_VT;
    size_t base = (size_t)blockIdx.x * HWN;
    __shared__ __half sm[64][65];
    int t = threadIdx.x;
    #pragma unroll
    for (int r = 0; r < 16; r++) {
        int idx = r * 256 + t;
        sm[idx >> 6][idx & 63] = src[base + idx];
    }
    __syncthreads();
    #pragma unroll
    for (int r = 0; r < 16; r++) {
        int idx = r * 256 + t;
        dst[base + idx] = sm[idx & 63][idx >> 6];
    }
}

// =====================================================================
// Logits HMMA core: S[m][n] = sum_d A[d][m]*B[d][n], 64x64x64.
// =====================================================================
__device__ __forceinline__ void logits_hmma(
    const __half* __restrict__ qg, const __half* __restrict__ kg_,
    __half* __restrict__ outp, size_t mStride)
{
    __shared__ uint32_t As[64][33];
    __shared__ uint32_t Bs[64][33];
    int t = threadIdx.x;
    #pragma unroll
    for (int r = 0; r < 8; r++) {
        int idx = r * 256 + t;
        int d2 = idx >> 6, x = idx & 63;
        size_t o0 = (size_t)(2 * d2) * HWN + x;
        As[x][d2] = packh2(qg[o0], qg[o0 + HWN]);
        Bs[x][d2] = packh2(kg_[o0], kg_[o0 + HWN]);
    }
    __syncthreads();
    int lane = t & 31, wid = t >> 5;
    int g = lane >> 2, tg = lane & 3;
    int wm = (wid >> 2) * 32, wn = (wid & 3) * 16;

    float c[2][2][4];
    #pragma unroll
    for (int mi = 0; mi < 2; mi++)
        #pragma unroll
        for (int ni = 0; ni < 2; ni++)
            #pragma unroll
            for (int e = 0; e < 4; e++) c[mi][ni][e] = 0.0f;

    #pragma unroll
    for (int ks = 0; ks < 4; ks++) {
        int k2 = ks * 8;
        uint32_t a[2][4], bb[2][2];
        #pragma unroll
        for (int mi = 0; mi < 2; mi++) {
            int row = wm + mi * 16 + g;
            a[mi][0] = As[row][k2 + tg];
            a[mi][1] = As[row + 8][k2 + tg];
            a[mi][2] = As[row][k2 + 4 + tg];
            a[mi][3] = As[row + 8][k2 + 4 + tg];
        }
        #pragma unroll
        for (int ni = 0; ni < 2; ni++) {
            int col = wn + ni * 8 + g;
            bb[ni][0] = Bs[col][k2 + tg];
            bb[ni][1] = Bs[col][k2 + 4 + tg];
        }
        #pragma unroll
        for (int mi = 0; mi < 2; mi++)
            #pragma unroll
            for (int ni = 0; ni < 2; ni++)
                mma_f16(c[mi][ni], a[mi], bb[ni]);
    }

    #pragma unroll
    for (int mi = 0; mi < 2; mi++) {
        int m0 = wm + mi * 16 + g;
        #pragma unroll
        for (int ni = 0; ni < 2; ni++) {
            int n = wn + ni * 8 + tg * 2;
            *(__half2*)(outp + (size_t)m0 * mStride + n) =
                __floats2half2_rn(c[mi][ni][0] * SCALE, c[mi][ni][1] * SCALE);
            *(__half2*)(outp + (size_t)(m0 + 8) * mStride + n) =
                __floats2half2_rn(c[mi][ni][2] * SCALE, c[mi][ni][3] * SCALE);
        }
    }
}

// Kernel 3: row logits. block (i, h, b).
__global__ __launch_bounds__(256) void logits_row_kernel()
{
    int i = blockIdx.x, h = blockIdx.y, b = blockIdx.z;
    size_t base  = ((size_t)(b * DQKV + h * DHH)) * HWN + i * WW;
    size_t pbase = (((size_t)((b * NHH + h) * HH + i)) * WW) * PLEN;
    logits_hmma(g_Q + base, g_K + base, g_P + pbase, PLEN);
}

// Kernel 4: column logits. block (j, h, b).
__global__ __launch_bounds__(256) void logits_col_kernel()
{
    int j = blockIdx.x, h = blockIdx.y, b = blockIdx.z;
    size_t base = ((size_t)(b * DQKV + h * DHH)) * HWN + j * HH;
    size_t pre  = ((size_t)((b * NHH + h) * HH) * WW + j) * PLEN + 64;
    logits_hmma(g_QT + base, g_KT + base, g_P + pre, (size_t)WW * PLEN);
}

// =====================================================================
// Kernel 5: softmax over 128 fp16 logits per query, in place.
// =====================================================================
__global__ __launch_bounds__(256) void softmax_kernel()
{
    size_t row = (size_t)blockIdx.x * 8 + (threadIdx.x >> 5);
    int lane = threadIdx.x & 31;
    __half* p = g_P + row * PLEN + lane * 4;
    float4 v = ldh4(p);
    float m = fmaxf(fmaxf(v.x, v.y), fmaxf(v.z, v.w));
    #pragma unroll
    for (int o = 16; o; o >>= 1) m = fmaxf(m, __shfl_xor_sync(0xffffffffu, m, o));
    v.x = __expf(v.x - m); v.y = __expf(v.y - m);
    v.z = __expf(v.z - m); v.w = __expf(v.w - m);
    float s = v.x + v.y + v.z + v.w;
    #pragma unroll
    for (int o = 16; o; o >>= 1) s += __shfl_xor_sync(0xffffffffu, s, o);
    float inv = 1.0f / s;
    v.x *= inv; v.y *= inv; v.z *= inv; v.w *= inv;
    sth4(p, v);
}

// =====================================================================
// Attention HMMA core: out[d][q] = sum_k V[d][k]*P[q][k], 64x64x64.
// =====================================================================
__device__ __forceinline__ void attn_hmma(
    const __half* __restrict__ vg, const __half* __restrict__ pg,
    size_t pStride, __half os[64][66])
{
    __shared__ uint32_t As[64][33];
    __shared__ uint32_t Bs[64][33];
    int t = threadIdx.x;
    #pragma unroll
    for (int r = 0; r < 8; r++) {
        int idx = r * 256 + t;
        int row = idx >> 5, k2 = idx & 31;
        As[row][k2] = *(const uint32_t*)(vg + (size_t)row * HWN + 2 * k2);
        Bs[row][k2] = *(const uint32_t*)(pg + (size_t)row * pStride + 2 * k2);
    }
    __syncthreads();
    int lane = t & 31, wid = t >> 5;
    int g = lane >> 2, tg = lane & 3;
    int wm = (wid >> 2) * 32, wn = (wid & 3) * 16;

    float c[2][2][4];
    #pragma unroll
    for (int mi = 0; mi < 2; mi++)
        #pragma unroll
        for (int ni = 0; ni < 2; ni++)
            #pragma unroll
            for (int e = 0; e < 4; e++) c[mi][ni][e] = 0.0f;

    #pragma unroll
    for (int ks = 0; ks < 4; ks++) {
        int k2 = ks * 8;
        uint32_t a[2][4], bb[2][2];
        #pragma unroll
        for (int mi = 0; mi < 2; mi++) {
            int row = wm + mi * 16 + g;
            a[mi][0] = As[row][k2 + tg];
            a[mi][1] = As[row + 8][k2 + tg];
            a[mi][2] = As[row][k2 + 4 + tg];
            a[mi][3] = As[row + 8][k2 + 4 + tg];
        }
        #pragma unroll
        for (int ni = 0; ni < 2; ni++) {
            int col = wn + ni * 8 + g;
            bb[ni][0] = Bs[col][k2 + tg];
            bb[ni][1] = Bs[col][k2 + 4 + tg];
        }
        #pragma unroll
        for (int mi = 0; mi < 2; mi++)
            #pragma unroll
            for (int ni = 0; ni < 2; ni++)
                mma_f16(c[mi][ni], a[mi], bb[ni]);
    }

    #pragma unroll
    for (int mi = 0; mi < 2; mi++) {
        int d0 = wm + mi * 16 + g;
        #pragma unroll
        for (int ni = 0; ni < 2; ni++) {
            int q = wn + ni * 8 + tg * 2;
            *(__half2*)&os[d0][q]     = __floats2half2_rn(c[mi][ni][0], c[mi][ni][1]);
            *(__half2*)&os[d0 + 8][q] = __floats2half2_rn(c[mi][ni][2], c[mi][ni][3]);
        }
    }
    __syncthreads();
}

// Kernel 6: row attention. block (i,h,b). out -> g_A [b][p][ch]
__global__ __launch_bounds__(256) void attn_row_kernel()
{
    int i = blockIdx.x, h = blockIdx.y, b = blockIdx.z;
    __shared__ __half os[64][66];
    size_t vbase = ((size_t)(b * DQKV + h * DHH)) * HWN + i * WW;
    size_t pbase = (((size_t)((b * NHH + h) * HH + i)) * WW) * PLEN;
    attn_hmma(g_V + vbase, g_P + pbase, PLEN, os);
    int t = threadIdx.x;
    int ty = t >> 4, tx = t & 15;
    int chb = h * DHH + ty * 4;
    #pragma unroll
    for (int cc = 0; cc < 4; cc++) {
        int q = tx * 4 + cc;
        int p = i * WW + q;
        uint2 u;
        *(__half2*)&u.x = __halves2half2(os[ty * 4 + 0][q], os[ty * 4 + 1][q]);
        *(__half2*)&u.y = __halves2half2(os[ty * 4 + 2][q], os[ty * 4 + 3][q]);
        *(uint2*)(g_A + ((size_t)b * HWN + p) * DQKV + chb) = u;
    }
}

// Kernel 7: column attention. block (j,h,b). out -> g_AT [b][p][ch]
__global__ __launch_bounds__(256) void attn_col_kernel()
{
    int j = blockIdx.x, h = blockIdx.y, b = blockIdx.z;
    __shared__ __half os[64][66];
    size_t vbase = ((size_t)(b * DQKV + h * DHH)) * HWN + j * HH;
    size_t pcol  = ((size_t)((b * NHH + h) * HH) * WW + j) * PLEN + 64;
    attn_hmma(g_VT + vbase, g_P + pcol, (size_t)WW * PLEN, os);
    int t = threadIdx.x;
    int ty = t >> 4, tx = t & 15;
    int chb = h * DHH + ty * 4;
    #pragma unroll
    for (int cc = 0; cc < 4; cc++) {
        int q = tx * 4 + cc;           // q = i
        int p = q * WW + j;
        uint2 u;
        *(__half2*)&u.x = __halves2half2(os[ty * 4 + 0][q], os[ty * 4 + 1][q]);
        *(__half2*)&u.y = __halves2half2(os[ty * 4 + 2][q], os[ty * 4 + 3][q]);
        *(uint2*)(g_AT + ((size_t)b * HWN + p) * DQKV + chb) = u;
    }
}

// =====================================================================
// Kernel 9: output projection + residual via fp16 HMMA m16n8k16.
// Block 128 ch x 128 p; K=512 in 16 chunks of 32 (pad 20).
// =====================================================================
__global__ __launch_bounds__(256, 2) void proj_mma(
    const float* __restrict__ x, const float* __restrict__ Wo,
    const float* __restrict__ bo, float* __restrict__ out)
{
    int pT = blockIdx.x, mT = blockIdx.y, b = blockIdx.z;
    int mOff = mT * 128;

    __shared__ uint32_t As[128][20];
    __shared__ uint32_t Bs[128][20];

    int t = threadIdx.x, lane = t & 31, wid = t >> 5;
    int g = lane >> 2, tig = lane & 3;
    int wm = (wid >> 2) * 64, wn = (wid & 3) * 32;

    const __half* a2w = g_A  + ((size_t)b * HWN + (size_t)pT * 128) * DQKV;
    const __half* a2h = g_AT + ((size_t)b * HWN + (size_t)pT * 128) * DQKV;

    float c[4][4][4];
    #pragma unroll
    for (int mi = 0; mi < 4; mi++)
        #pragma unroll
        for (int ni = 0; ni < 4; ni++)
            #pragma unroll
            for (int e = 0; e < 4; e++) c[mi][ni][e] = 0.0f;

    for (int c0 = 0; c0 < 16; c0++) {
        int kBase = c0 * 32;
        #pragma unroll
        for (int r = 0; r < 4; r++) {
            int idx = r * 256 + t;
            int row = idx >> 3, q = idx & 7;
            int k4 = kBase + q * 4;
            float4 va = *(const float4*)(Wo + (size_t)(mOff + row) * DQKV + k4);
            As[row][q * 2]     = packf2h(va.x, va.y);
            As[row][q * 2 + 1] = packf2h(va.z, va.w);
            float4 vb = ldh4(a2w + (size_t)row * DQKV + k4);
            float4 vh = ldh4(a2h + (size_t)row * DQKV + k4);
            Bs[row][q * 2]     = packf2h(vb.x + vh.x, vb.y + vh.y);
            Bs[row][q * 2 + 1] = packf2h(vb.z + vh.z, vb.w + vh.w);
        }
        __syncthreads();
        #pragma unroll
        for (int ks = 0; ks < 2; ks++) {
            int kk = ks * 8;
            uint32_t a[4][4], bfr[4][2];
            #pragma unroll
            for (int mi = 0; mi < 4; mi++) {
                int row = wm + mi * 16 + g;
                a[mi][0] = As[row][kk + tig];
                a[mi][1] = As[row + 8][kk + tig];
                a[mi][2] = As[row][kk + tig + 4];
                a[mi][3] = As[row + 8][kk + tig + 4];
            }
            #pragma unroll
            for (int ni = 0; ni < 4; ni++) {
                int col = wn + ni * 8 + g;
                bfr[ni][0] = Bs[col][kk + tig];
                bfr[ni][1] = Bs[col][kk + tig + 4];
            }
            #pragma unroll
            for (int mi = 0; mi < 4; mi++)
                #pragma unroll
                for (int ni = 0; ni < 4; ni++)
                    mma_f16(c[mi][ni], a[mi], bfr[ni]);
        }
        __syncthreads();
    }

    #pragma unroll
    for (int mi = 0; mi < 4; mi++) {
        int row0 = wm + mi * 16 + g;
        int ch0 = mOff + row0;
        float bi0 = bo[ch0];
        float bi1 = bo[ch0 + 8];
        size_t base0 = ((size_t)b * CC + ch0) * HWN + (size_t)pT * 128;
        size_t base1 = base0 + (size_t)8 * HWN;
        #pragma unroll
        for (int ni = 0; ni < 4; ni++) {
            int col = wn + ni * 8 + tig * 2;
            float2 x0 = *(const float2*)(x + base0 + col);
            float2 x1 = *(const float2*)(x + base1 + col);
            float2 v0 = make_float2(c[mi][ni][0] + bi0 + x0.x,
                                    c[mi][ni][1] + bi0 + x0.y);
            float2 v1 = make_float2(c[mi][ni][2] + bi1 + x1.x,
                                    c[mi][ni][3] + bi1 + x1.y);
            *(float2*)(out + base0 + col) = v0;
            *(float2*)(out + base1 + col) = v1;
        }
    }
}

// =====================================================================
extern "C" void kernel_launch(void* const* d_in, const int* in_sizes, int n_in,
                              void* d_out, int out_size)
{
    const float* x   = (const float*)d_in[0];
    const float* pos = (const float*)d_in[1];
    const float* Wk  = (const float*)d_in[2];
    const float* bk  = (const float*)d_in[3];
    const float* Wq  = (const float*)d_in[4];
    const float* bq  = (const float*)d_in[5];
    const float* Wv  = (const float*)d_in[6];
    const float* bv  = (const float*)d_in[7];
    const float* Wo  = (const float*)d_in[8];
    const float* bo  = (const float*)d_in[9];
    float* out = (float*)d_out;

    xpose_x<<<dim3(64, 5, BB), 256>>>(x, pos);
    qkv_mma<<<dim3(32, 12, BB), 256>>>(Wq, bq, Wk, bk, Wv, bv);
    transpose3_kernel<<<dim3(BB * DQKV, 3), 256>>>();
    logits_row_kernel<<<dim3(HH, NHH, BB), 256>>>();
    logits_col_kernel<<<dim3(WW, NHH, BB), 256>>>();
    softmax_kernel<<<65536, 256>>>();
    attn_row_kernel<<<dim3(HH, NHH, BB), 256>>>();
    attn_col_kernel<<<dim3(WW, NHH, BB), 256>>>();
    proj_mma<<<dim3(32, 2, BB), 256>>>(x, Wo, bo, out);
}